// round 14
// baseline (speedup 1.0000x reference)
#include <cuda_runtime.h>
#include <cuda_fp16.h>
#include <cstdint>

#define CL 512
#define CE 512
#define NPAIR 128
#define NB 32
#define ATTN_ELEMS (NPAIR * CL * CL)
#define OUT_ELEMS (NB * 1024)
#define SCALE_F 0.044194173824159216f

// ---------------- scratch (device globals; alloc-free rule) ----------------
__device__ float g_pooled[NB * 4096];
__device__ float g_attn_scratch[ATTN_ELEMS];
__device__ float g_out_dummy[OUT_ELEMS];
__device__ float g_rowsum[NPAIR * CL];
__device__ float g_psum[8 * NPAIR * CL];
__device__ float g_pmax[8 * NPAIR * CL];
__device__ float g_vmean[NPAIR * CE];
__device__ float g_opart[8 * NB * 1024];
__device__ int g_qlen[32];
__device__ int g_klen[128];
__device__ __half g_qh[NB * CL * CE];     // x1 fp16
__device__ __half g_kh[NPAIR * CL * CE];  // x2 fp16
__device__ __half g_ah[NPAIR * CL * CL];  // UNNORMALIZED exp fp16
__device__ __half g_sh[NPAIR * CL * CE];  // x1 - xa fp16
__device__ __half g_mh[NPAIR * CL * CE];  // x1 * xa fp16
__device__ __half g_fwh[1024 * 512];      // fusion_w fp16

// ---------------- PTX helpers ----------------
__device__ __forceinline__ uint32_t smem_u32(const void* p) {
    uint32_t a;
    asm("{ .reg .u64 t; cvta.to.shared.u64 t, %1; cvt.u32.u64 %0, t; }" : "=r"(a) : "l"(p));
    return a;
}
__device__ __forceinline__ void cp_async16(uint32_t dst, const void* src) {
    asm volatile("cp.async.ca.shared.global [%0], [%1], 16;" :: "r"(dst), "l"(src));
}
#define CP_COMMIT() asm volatile("cp.async.commit_group;" ::: "memory")
#define CP_WAIT(n)  asm volatile("cp.async.wait_group %0;" :: "n"(n) : "memory")

__device__ __forceinline__ void ldm_x4(uint32_t* r, uint32_t addr) {
    asm volatile("ldmatrix.sync.aligned.m8n8.x4.shared.b16 {%0,%1,%2,%3}, [%4];"
                 : "=r"(r[0]), "=r"(r[1]), "=r"(r[2]), "=r"(r[3]) : "r"(addr));
}
__device__ __forceinline__ void ldm_x4t(uint32_t* r, uint32_t addr) {
    asm volatile("ldmatrix.sync.aligned.m8n8.x4.trans.shared.b16 {%0,%1,%2,%3}, [%4];"
                 : "=r"(r[0]), "=r"(r[1]), "=r"(r[2]), "=r"(r[3]) : "r"(addr));
}
__device__ __forceinline__ void mma_f16(float* c, const uint32_t* a, const uint32_t* b) {
    asm volatile(
        "mma.sync.aligned.m16n8k16.row.col.f32.f16.f16.f32 "
        "{%0,%1,%2,%3}, {%4,%5,%6,%7}, {%8,%9}, {%0,%1,%2,%3};"
        : "+f"(c[0]), "+f"(c[1]), "+f"(c[2]), "+f"(c[3])
        : "r"(a[0]), "r"(a[1]), "r"(a[2]), "r"(a[3]), "r"(b[0]), "r"(b[1]));
}

// ---------------- smem geometry ----------------
// scores: 4-stage ring, stage = Q(128x32k) + K(128x32k)
#define PITCHB 80
#define TILE_B (128 * PITCHB)           // 10240
#define SC_STAGE (2 * TILE_B)           // 20480
#define SC_RS_OFF (4 * SC_STAGE)        // 81920
#define SC_RINV_OFF (SC_RS_OFF + 2048)
#define SC_SMEM (SC_RINV_OFF + 512)     // 84480
// av / fusion: 64x256 tiles, 4-stage ring, stage = A(64x32k) + B(32k x 256)
#define AF_A_SZ (64 * 80)               // 5120
#define AF_B_PITCH 528
#define AF_B_SZ (32 * AF_B_PITCH)       // 16896
#define AF_STAGE (AF_A_SZ + AF_B_SZ)    // 22016
#define AF_RING (4 * AF_STAGE)          // 88064
#define AV_SMEM AF_RING
#define FU_RED_OFF AF_RING
#define FU_SMEM (FU_RED_OFF + 4096)     // 92160

// ---------------- length normalization ----------------
__global__ void k_lens(const unsigned int* __restrict__ x1l,
                       const unsigned int* __restrict__ x2l) {
    __shared__ int is64;
    int t = threadIdx.x;
    if (t == 0) {
        int all0 = 1;
        for (int i = 1; i < 128; i += 2)
            if (x2l[i] != 0u) { all0 = 0; break; }
        is64 = all0;
    }
    __syncthreads();
    if (t < 32)  g_qlen[t] = (int)(is64 ? x1l[2 * t] : x1l[t]);
    if (t < 128) g_klen[t] = (int)(is64 ? x2l[2 * t] : x2l[t]);
}

// ---------------- per-pair V colmeans + fused x2 -> fp16 conversion ----------------
__global__ void k_vmean(const float* __restrict__ x2) {
    int p = blockIdx.x, e = threadIdx.x;
    const float* base = x2 + (size_t)p * 262144 + e;
    __half* kh = g_kh + (size_t)p * 262144 + e;
    float s0 = 0.f, s1 = 0.f, s2 = 0.f, s3 = 0.f;
    for (int k = 0; k < 512; k += 4) {
        float v0 = base[(k + 0) * 512];
        float v1 = base[(k + 1) * 512];
        float v2 = base[(k + 2) * 512];
        float v3 = base[(k + 3) * 512];
        s0 += v0; s1 += v1; s2 += v2; s3 += v3;
        kh[(k + 0) * 512] = __float2half(v0);
        kh[(k + 1) * 512] = __float2half(v1);
        kh[(k + 2) * 512] = __float2half(v2);
        kh[(k + 3) * 512] = __float2half(v3);
    }
    g_vmean[p * 512 + e] = (s0 + s1 + s2 + s3) * (1.f / 512.f);
}

// ---------------- fp32 -> fp16 (single) ----------------
__global__ void k_cvt1(const float* __restrict__ src, __half* __restrict__ hi, int n4) {
    int i = blockIdx.x * blockDim.x + threadIdx.x;
    if (i >= n4) return;
    float4 v = ((const float4*)src)[i];
    ((__half2*)hi)[2 * i] = __floats2half2_rn(v.x, v.y);
    ((__half2*)hi)[2 * i + 1] = __floats2half2_rn(v.z, v.w);
}

// ---------------- scores: Q@K^T (1-term fp16), masked exp -> fp16 + fp32 attn -----
__global__ __launch_bounds__(256, 2) void k_scores_mma(float* __restrict__ attn) {
    extern __shared__ char smem[];
    uint32_t sb = smem_u32(smem);
    int t = threadIdx.x, lane = t & 31, wid = t >> 5;
    int wm = wid >> 2, wn = wid & 3;
    int p = blockIdx.y, x1i = p & 31;
    int qt = blockIdx.x, q0 = qt * 128;
    int qlen = g_qlen[x1i], klen = g_klen[p];

    bool all_masked = (q0 >= qlen) || (klen == 0);
    int n_nt = all_masked ? 0 : min(4, (klen + 127) >> 7);
    int n_stages = n_nt * 16;

    const char* Qh = (const char*)(g_qh + (size_t)x1i * 262144);
    const char* Kh = (const char*)(g_kh + (size_t)p * 262144);

    float acc[4][4][4];
#pragma unroll
    for (int a = 0; a < 4; a++)
#pragma unroll
        for (int b = 0; b < 4; b++)
#pragma unroll
            for (int c = 0; c < 4; c++) acc[a][b][c] = 0.f;
    float rsum[4][2];
#pragma unroll
    for (int a = 0; a < 4; a++) rsum[a][0] = rsum[a][1] = 0.f;

    auto load_stage = [&](int s) {
        int nt = s >> 4, ec = s & 15;
        uint32_t bb = sb + (s & 3) * SC_STAGE;
#pragma unroll
        for (int h = 0; h < 2; h++) {
            int idx = h * 256 + t;
            int row = idx >> 2, q = (idx & 3) * 16;
            uint32_t dst = row * PITCHB + q;
            size_t asrc = (size_t)(q0 + row) * 1024 + ec * 64 + q;
            size_t bsrc = (size_t)(nt * 128 + row) * 1024 + ec * 64 + q;
            cp_async16(bb + dst, Qh + asrc);
            cp_async16(bb + TILE_B + dst, Kh + bsrc);
        }
    };

    if (n_stages > 0) {
        load_stage(0);
        CP_COMMIT();
        if (n_stages > 1) load_stage(1);
        CP_COMMIT();
        if (n_stages > 2) load_stage(2);
        CP_COMMIT();
    }

    __half2* AH = (__half2*)(g_ah + (size_t)p * 262144);

    for (int s = 0; s < n_stages; s++) {
        CP_WAIT(2);
        __syncthreads();
        if (s + 3 < n_stages) load_stage(s + 3);
        CP_COMMIT();
        uint32_t bb = sb + (s & 3) * SC_STAGE;
#pragma unroll
        for (int kk = 0; kk < 2; kk++) {
            uint32_t aBase = bb + (wm * 64 + (lane & 15)) * PITCHB + (lane >> 4) * 16 +
                             kk * 32;
            uint32_t aHi[4][4];
#pragma unroll
            for (int mt = 0; mt < 4; mt++)
                ldm_x4(aHi[mt], aBase + mt * 16 * PITCHB);
            uint32_t bBase = bb + TILE_B +
                             (wn * 32 + ((lane >> 4) & 1) * 8 + (lane & 7)) * PITCHB +
                             ((lane >> 3) & 1) * 16 + kk * 32;
#pragma unroll
            for (int pr = 0; pr < 2; pr++) {
                uint32_t bH[4];
                ldm_x4(bH, bBase + pr * 16 * PITCHB);
#pragma unroll
                for (int mt = 0; mt < 4; mt++)
#pragma unroll
                    for (int n2 = 0; n2 < 2; n2++)
                        mma_f16(acc[mt][pr * 2 + n2], aHi[mt], bH + 2 * n2);
            }
        }
        if ((s & 15) == 15) {
            int nt = s >> 4;
            int nb = nt * 128 + wn * 32;
#pragma unroll
            for (int mt = 0; mt < 4; mt++) {
                int r0 = q0 + wm * 64 + mt * 16 + (lane >> 2);
                bool fm0 = (r0 >= qlen);
                bool fm1 = ((r0 + 8) >= qlen);
#pragma unroll
                for (int ntl = 0; ntl < 4; ntl++) {
                    int col = nb + ntl * 8 + (lane & 3) * 2;
                    float* cc = acc[mt][ntl];
                    float e0 = fm0 ? 1.f : ((col < klen) ? __expf(cc[0] * SCALE_F) : 0.f);
                    float e1 = fm0 ? 1.f : ((col + 1 < klen) ? __expf(cc[1] * SCALE_F) : 0.f);
                    float e2 = fm1 ? 1.f : ((col < klen) ? __expf(cc[2] * SCALE_F) : 0.f);
                    float e3 = fm1 ? 1.f : ((col + 1 < klen) ? __expf(cc[3] * SCALE_F) : 0.f);
                    rsum[mt][0] += e0 + e1;
                    rsum[mt][1] += e2 + e3;
                    AH[((size_t)r0 * 512 + col) >> 1] = __floats2half2_rn(e0, e1);
                    AH[((size_t)(r0 + 8) * 512 + col) >> 1] = __floats2half2_rn(e2, e3);
                    cc[0] = cc[1] = cc[2] = cc[3] = 0.f;
                }
            }
        }
    }

    // fill skipped 128-col blocks: masked rows -> exp 1, live rows -> 0
    {
        __half* AHB = g_ah + (size_t)p * 262144;
        const uint32_t ONE2 = 0x3C003C00u;
        uint4 vone = make_uint4(ONE2, ONE2, ONE2, ONE2);
        uint4 vzer = make_uint4(0u, 0u, 0u, 0u);
        for (int nt = n_nt; nt < 4; nt++) {
            for (int i = t; i < 2048; i += 256) {
                int row = i >> 4, c8 = (i & 15) * 8;
                bool mr = all_masked || ((q0 + row) >= qlen);
                size_t o = (size_t)(q0 + row) * 512 + nt * 128 + c8;
                *(uint4*)(AHB + o) = mr ? vone : vzer;
            }
        }
    }

    __syncthreads();
    float* rs = (float*)(smem + SC_RS_OFF);
    float* rinv = (float*)(smem + SC_RINV_OFF);
#pragma unroll
    for (int mt = 0; mt < 4; mt++)
#pragma unroll
        for (int ri = 0; ri < 2; ri++) {
            float v = rsum[mt][ri];
            v += __shfl_xor_sync(0xffffffffu, v, 1);
            v += __shfl_xor_sync(0xffffffffu, v, 2);
            if ((lane & 3) == 0)
                rs[(wm * 64 + mt * 16 + ri * 8 + (lane >> 2)) * 4 + wn] = v;
        }
    __syncthreads();
    if (t < 128) {
        float s = rs[t * 4] + rs[t * 4 + 1] + rs[t * 4 + 2] + rs[t * 4 + 3];
        bool mr = all_masked || ((q0 + t) >= qlen);
        s += (float)(4 - n_nt) * 128.f * (mr ? 1.f : 0.f);
        g_rowsum[p * 512 + q0 + t] = s;
        rinv[t] = s > 0.f ? 1.f / s : 0.f;
    }
    __syncthreads();

    // normalize tail: fp32 attn from just-written exp (L2-hot) + rowsum
    {
        const __half2* AHB = (const __half2*)(g_ah + (size_t)p * 262144);
        float* AT = attn + (size_t)p * 262144;
        for (int i = t; i < 128 * 128; i += 256) {
            int row = i >> 7, c4 = (i & 127) * 4;
            float inv = rinv[row];
            size_t o = (size_t)(q0 + row) * 512 + c4;
            float2 f0 = __half22float2(AHB[o >> 1]);
            float2 f1 = __half22float2(AHB[(o >> 1) + 1]);
            float4 v;
            v.x = f0.x * inv;
            v.y = f0.y * inv;
            v.z = f1.x * inv;
            v.w = f1.y * inv;
            *(float4*)(AT + o) = v;
        }
    }
}

// ---------------- x1_att = exp @ V / rowsum (64x256 tile); emits cat fp16 ----------
__global__ __launch_bounds__(256, 2) void k_av_mma(const float* __restrict__ x1) {
    extern __shared__ char smem[];
    uint32_t sb = smem_u32(smem);
    int t = threadIdx.x, lane = t & 31, wid = t >> 5;
    int wm = wid >> 2, wn = wid & 3;
    int p = blockIdx.z, x1i = p & 31;
    int q0 = blockIdx.y * 64, e0 = blockIdx.x * 256;
    int qlen = g_qlen[x1i], klen = g_klen[p];

    bool all_masked = (q0 >= qlen) || (klen == 0);
    int n_stage = all_masked ? 0 : min(16, (klen + 31) >> 5);

    const char* Ah = (const char*)(g_ah + (size_t)p * 262144);
    const char* Vh = (const char*)(g_kh + (size_t)p * 262144);

    float acc[2][8][4];
#pragma unroll
    for (int a = 0; a < 2; a++)
#pragma unroll
        for (int b = 0; b < 8; b++)
#pragma unroll
            for (int c = 0; c < 4; c++) acc[a][b][c] = 0.f;

    auto load_stage = [&](int s) {
        uint32_t bb = sb + (s & 3) * AF_STAGE;
        {
            int row = t >> 2, ch = t & 3;
            size_t off = (size_t)(q0 + row) * 1024 + s * 64 + ch * 16;
            cp_async16(bb + row * 80 + ch * 16, Ah + off);
        }
#pragma unroll
        for (int h = 0; h < 4; h++) {
            int idx = h * 256 + t;
            int row = idx >> 5, ch = idx & 31;
            size_t off = (size_t)(s * 32 + row) * 1024 + e0 * 2 + ch * 16;
            cp_async16(bb + AF_A_SZ + row * AF_B_PITCH + ch * 16, Vh + off);
        }
    };

    if (n_stage > 0) {
        load_stage(0);
        CP_COMMIT();
        if (n_stage > 1) load_stage(1);
        CP_COMMIT();
        if (n_stage > 2) load_stage(2);
        CP_COMMIT();
    }

    for (int s = 0; s < n_stage; s++) {
        CP_WAIT(2);
        __syncthreads();
        if (s + 3 < n_stage) load_stage(s + 3);
        CP_COMMIT();
        uint32_t bb = sb + (s & 3) * AF_STAGE;
#pragma unroll
        for (int kk = 0; kk < 2; kk++) {
            uint32_t aBase = bb + (wm * 32 + (lane & 15)) * 80 + ((lane >> 4) & 1) * 16 +
                             kk * 32;
            uint32_t aHi[2][4];
#pragma unroll
            for (int mt = 0; mt < 2; mt++)
                ldm_x4(aHi[mt], aBase + mt * 16 * 80);
            uint32_t bBase = bb + AF_A_SZ + (kk * 16 + (lane & 15)) * AF_B_PITCH +
                             wn * 128 + ((lane >> 4) & 1) * 16;
#pragma unroll
            for (int pr = 0; pr < 4; pr++) {
                uint32_t bH[4];
                ldm_x4t(bH, bBase + pr * 32);
#pragma unroll
                for (int mt = 0; mt < 2; mt++)
#pragma unroll
                    for (int n2 = 0; n2 < 2; n2++)
                        mma_f16(acc[mt][pr * 2 + n2], aHi[mt], bH + 2 * n2);
            }
        }
    }

    // epilogue: xa = acc/rowsum (masked rows: colmean V) -> (x1-xa, x1*xa) fp16
    const float* X1 = x1 + (size_t)x1i * 262144;
    const float* VM = g_vmean + p * 512;
    __half2* Sh = (__half2*)(g_sh + (size_t)p * 262144);
    __half2* Mh = (__half2*)(g_mh + (size_t)p * 262144);
#pragma unroll
    for (int mt = 0; mt < 2; mt++) {
#pragma unroll
        for (int hh = 0; hh < 2; hh++) {
            int r = q0 + wm * 32 + mt * 16 + (lane >> 2) + hh * 8;
            bool mr = all_masked || (r >= qlen);
            float inv = 0.f;
            if (!mr) inv = 1.f / g_rowsum[p * 512 + r];
#pragma unroll
            for (int ntl = 0; ntl < 8; ntl++) {
                float* cc = acc[mt][ntl];
                int c = e0 + wn * 64 + ntl * 8 + (lane & 3) * 2;
                float2 u = *(const float2*)(X1 + (size_t)r * 512 + c);
                float xa0, xa1;
                if (mr) {
                    float2 vm = *(const float2*)(VM + c);
                    xa0 = vm.x;
                    xa1 = vm.y;
                } else {
                    xa0 = cc[hh * 2] * inv;
                    xa1 = cc[hh * 2 + 1] * inv;
                }
                size_t o = ((size_t)r * 512 + c) >> 1;
                Sh[o] = __floats2half2_rn(u.x - xa0, u.y - xa1);
                Mh[o] = __floats2half2_rn(u.x * xa0, u.y * xa1);
            }
        }
    }
}

// ---------------- fusion GEMM (64x256 tile) + bias/relu + partial pooling ----------
__global__ __launch_bounds__(256, 2) void k_fusion_mma(const float* __restrict__ fb) {
    extern __shared__ char smem[];
    uint32_t sb = smem_u32(smem);
    int t = threadIdx.x, lane = t & 31, wid = t >> 5;
    int wm = wid >> 2, wn = wid & 3;
    int p = blockIdx.z;
    int qt = blockIdx.y, q0 = qt * 64, e0 = blockIdx.x * 256;

    const char* Sh = (const char*)(g_sh + (size_t)p * 262144);
    const char* Mh = (const char*)(g_mh + (size_t)p * 262144);
    const char* Wh = (const char*)g_fwh;

    float acc[2][8][4];
#pragma unroll
    for (int a = 0; a < 2; a++)
#pragma unroll
        for (int b = 0; b < 8; b++)
#pragma unroll
            for (int c = 0; c < 4; c++) acc[a][b][c] = 0.f;

    auto load_stage = [&](int s) {
        uint32_t bb = sb + (s & 3) * AF_STAGE;
        const char* ah = (s < 16) ? Sh : Mh;
        int kc = (s & 15) * 64;
        {
            int row = t >> 2, ch = t & 3;
            size_t off = (size_t)(q0 + row) * 1024 + kc + ch * 16;
            cp_async16(bb + row * 80 + ch * 16, ah + off);
        }
#pragma unroll
        for (int h = 0; h < 4; h++) {
            int idx = h * 256 + t;
            int row = idx >> 5, ch = idx & 31;
            size_t off = (size_t)(s * 32 + row) * 1024 + e0 * 2 + ch * 16;
            cp_async16(bb + AF_A_SZ + row * AF_B_PITCH + ch * 16, Wh + off);
        }
    };

    load_stage(0);
    CP_COMMIT();
    load_stage(1);
    CP_COMMIT();
    load_stage(2);
    CP_COMMIT();

    for (int s = 0; s < 32; s++) {
        CP_WAIT(2);
        __syncthreads();
        if (s + 3 < 32) load_stage(s + 3);
        CP_COMMIT();
        uint32_t bb = sb + (s & 3) * AF_STAGE;
#pragma unroll
        for (int kk = 0; kk < 2; kk++) {
            uint32_t aBase = bb + (wm * 32 + (lane & 15)) * 80 + ((lane >> 4) & 1) * 16 +
                             kk * 32;
            uint32_t aHi[2][4];
#pragma unroll
            for (int mt = 0; mt < 2; mt++)
                ldm_x4(aHi[mt], aBase + mt * 16 * 80);
            uint32_t bBase = bb + AF_A_SZ + (kk * 16 + (lane & 15)) * AF_B_PITCH +
                             wn * 128 + ((lane >> 4) & 1) * 16;
#pragma unroll
            for (int pr = 0; pr < 4; pr++) {
                uint32_t bH[4];
                ldm_x4t(bH, bBase + pr * 32);
#pragma unroll
                for (int mt = 0; mt < 2; mt++)
#pragma unroll
                    for (int n2 = 0; n2 < 2; n2++)
                        mma_f16(acc[mt][pr * 2 + n2], aHi[mt], bH + 2 * n2);
            }
        }
    }

    // bias + relu + pool over this block's 64 rows
    float psum[8][2], pmax[8][2];
#pragma unroll
    for (int ntl = 0; ntl < 8; ntl++) {
        psum[ntl][0] = psum[ntl][1] = 0.f;
        pmax[ntl][0] = pmax[ntl][1] = 0.f;
    }
#pragma unroll
    for (int ntl = 0; ntl < 8; ntl++) {
        int c = e0 + wn * 64 + ntl * 8 + (lane & 3) * 2;
        float b0 = fb[c], b1 = fb[c + 1];
#pragma unroll
        for (int mt = 0; mt < 2; mt++) {
            float* cc = acc[mt][ntl];
            float v0 = fmaxf(cc[0] + b0, 0.f);
            float v1 = fmaxf(cc[1] + b1, 0.f);
            float v2 = fmaxf(cc[2] + b0, 0.f);
            float v3 = fmaxf(cc[3] + b1, 0.f);
            psum[ntl][0] += v0 + v2;
            psum[ntl][1] += v1 + v3;
            pmax[ntl][0] = fmaxf(pmax[ntl][0], fmaxf(v0, v2));
            pmax[ntl][1] = fmaxf(pmax[ntl][1], fmaxf(v1, v3));
        }
    }
    __syncthreads();
    float* redS = (float*)(smem + FU_RED_OFF);
    float* redM = redS + 512;
#pragma unroll
    for (int ntl = 0; ntl < 8; ntl++)
#pragma unroll
        for (int j = 0; j < 2; j++) {
            float s = psum[ntl][j], m = pmax[ntl][j];
            s += __shfl_xor_sync(0xffffffffu, s, 4);
            s += __shfl_xor_sync(0xffffffffu, s, 8);
            s += __shfl_xor_sync(0xffffffffu, s, 16);
            m = fmaxf(m, __shfl_xor_sync(0xffffffffu, m, 4));
            m = fmaxf(m, __shfl_xor_sync(0xffffffffu, m, 8));
            m = fmaxf(m, __shfl_xor_sync(0xffffffffu, m, 16));
            if (lane < 4) {
                int col = wn * 64 + ntl * 8 + lane * 2 + j;
                redS[wm * 256 + col] = s;
                redM[wm * 256 + col] = m;
            }
        }
    __syncthreads();
    {
        float s = redS[t] + redS[256 + t];
        float m = fmaxf(redM[t], redM[256 + t]);
        int idx = (p * 8 + qt) * 512 + e0 + t;
        g_psum[idx] = s;
        g_pmax[idx] = m;
    }
}

// ---------------- pool finalize ----------------
__global__ void k_pool(void) {
    int p = blockIdx.x, e = threadIdx.x;
    float s = 0.f, m = 0.f;
#pragma unroll
    for (int qt = 0; qt < 8; qt++) {
        int idx = (p * 8 + qt) * 512 + e;
        s += g_psum[idx];
        m = fmaxf(m, g_pmax[idx]);
    }
    int base = (p >> 2) * 4096 + (p & 3) * 512 + e;
    g_pooled[base] = s * (1.0f / 512.0f);
    g_pooled[base + 2048] = m;
}

// ---------------- out GEMM: k-split partials ----------------
__global__ __launch_bounds__(256) void k_out_part(const float* __restrict__ ow) {
    __shared__ float sp[512];
    int b = blockIdx.x, ks = blockIdx.y, t = threadIdx.x;
    for (int i = t; i < 512; i += 256) sp[i] = g_pooled[b * 4096 + ks * 512 + i];
    __syncthreads();
    int col = t * 4;
    float4 acc = make_float4(0.f, 0.f, 0.f, 0.f);
#pragma unroll 8
    for (int c = 0; c < 512; c++) {
        float pv = sp[c];
        float4 w = *(const float4*)(ow + (size_t)(ks * 512 + c) * 1024 + col);
        acc.x += pv * w.x;
        acc.y += pv * w.y;
        acc.z += pv * w.z;
        acc.w += pv * w.w;
    }
    *(float4*)(g_opart + ((size_t)ks * 32 + b) * 1024 + col) = acc;
}

// ---------------- out finalize: fixed-order sum + bias + relu ----------------
__global__ __launch_bounds__(256) void k_out_fin(const float* __restrict__ ob,
                                                 float* __restrict__ outp) {
    int b = blockIdx.x, col = threadIdx.x * 4;
    float4 acc = *(const float4*)(ob + col);
#pragma unroll
    for (int ks = 0; ks < 8; ks++) {
        float4 v = *(const float4*)(g_opart + ((size_t)ks * 32 + b) * 1024 + col);
        acc.x += v.x;
        acc.y += v.y;
        acc.z += v.z;
        acc.w += v.w;
    }
    acc.x = fmaxf(acc.x, 0.f);
    acc.y = fmaxf(acc.y, 0.f);
    acc.z = fmaxf(acc.z, 0.f);
    acc.w = fmaxf(acc.w, 0.f);
    *(float4*)(outp + b * 1024 + col) = acc;
}

extern "C" void kernel_launch(void* const* d_in, const int* in_sizes, int n_in,
                              void* d_out, int out_size) {
    const float* x1 = (const float*)d_in[0];
    const float* x2 = (const float*)d_in[1];
    const unsigned int* x1_len = (const unsigned int*)d_in[2];
    const unsigned int* x2_len = (const unsigned int*)d_in[3];
    const float* fw = (const float*)d_in[4];
    const float* fb = (const float*)d_in[5];
    const float* ow = (const float*)d_in[6];
    const float* ob = (const float*)d_in[7];

    float* outp = (float*)d_out;
    float* attn;
    if (out_size >= OUT_ELEMS + ATTN_ELEMS) {
        attn = outp + OUT_ELEMS;
    } else if (out_size >= ATTN_ELEMS) {
        attn = outp;
        void* dp = nullptr;
        cudaGetSymbolAddress(&dp, g_out_dummy);
        outp = (float*)dp;
    } else {
        void* dp = nullptr;
        cudaGetSymbolAddress(&dp, g_attn_scratch);
        attn = (float*)dp;
    }

    void *qh, *fwh;
    cudaGetSymbolAddress(&qh, g_qh);
    cudaGetSymbolAddress(&fwh, g_fwh);

    cudaFuncSetAttribute(k_scores_mma, cudaFuncAttributeMaxDynamicSharedMemorySize, SC_SMEM);
    cudaFuncSetAttribute(k_av_mma, cudaFuncAttributeMaxDynamicSharedMemorySize, AV_SMEM);
    cudaFuncSetAttribute(k_fusion_mma, cudaFuncAttributeMaxDynamicSharedMemorySize, FU_SMEM);

    k_lens<<<1, 128>>>(x1_len, x2_len);
    k_vmean<<<NPAIR, 512>>>(x2);
    k_cvt1<<<8192, 256>>>(x1, (__half*)qh, 2097152);
    k_cvt1<<<512, 256>>>(fw, (__half*)fwh, 131072);
    k_scores_mma<<<dim3(4, NPAIR), 256, SC_SMEM>>>(attn);
    k_av_mma<<<dim3(2, 8, NPAIR), 256, AV_SMEM>>>(x1);
    k_fusion_mma<<<dim3(2, 8, NPAIR), 256, FU_SMEM>>>(fb);
    k_pool<<<NPAIR, 512>>>();
    k_out_part<<<dim3(NB, 8), 256>>>(ow);
    k_out_fin<<<NB, 256>>>(ob, outp);
}

// round 15
// speedup vs baseline: 1.0084x; 1.0084x over previous
#include <cuda_runtime.h>
#include <cuda_fp16.h>
#include <cstdint>

#define CL 512
#define CE 512
#define NPAIR 128
#define NB 32
#define ATTN_ELEMS (NPAIR * CL * CL)
#define OUT_ELEMS (NB * 1024)
#define SCALE_F 0.044194173824159216f

// ---------------- scratch (device globals; alloc-free rule) ----------------
__device__ float g_pooled[NB * 4096];
__device__ float g_attn_scratch[ATTN_ELEMS];
__device__ float g_out_dummy[OUT_ELEMS];
__device__ float g_rowsum[NPAIR * CL];
__device__ float g_psum[4 * NPAIR * CL];
__device__ float g_pmax[4 * NPAIR * CL];
__device__ float g_vmean[NPAIR * CE];
__device__ float g_opart[8 * NB * 1024];
__device__ int g_qlen[32];
__device__ int g_klen[128];
__device__ __half g_qh[NB * CL * CE];     // x1 fp16
__device__ __half g_kh[NPAIR * CL * CE];  // x2 fp16
__device__ __half g_ah[NPAIR * CL * CL];  // UNNORMALIZED exp fp16
__device__ __half g_sh[NPAIR * CL * CE];  // x1 - xa fp16
__device__ __half g_mh[NPAIR * CL * CE];  // x1 * xa fp16
__device__ __half g_fwh[1024 * 512];      // fusion_w fp16

// ---------------- PTX helpers ----------------
__device__ __forceinline__ uint32_t smem_u32(const void* p) {
    uint32_t a;
    asm("{ .reg .u64 t; cvta.to.shared.u64 t, %1; cvt.u32.u64 %0, t; }" : "=r"(a) : "l"(p));
    return a;
}
__device__ __forceinline__ void cp_async16(uint32_t dst, const void* src) {
    asm volatile("cp.async.ca.shared.global [%0], [%1], 16;" :: "r"(dst), "l"(src));
}
#define CP_COMMIT() asm volatile("cp.async.commit_group;" ::: "memory")
#define CP_WAIT(n)  asm volatile("cp.async.wait_group %0;" :: "n"(n) : "memory")

__device__ __forceinline__ void ldm_x4(uint32_t* r, uint32_t addr) {
    asm volatile("ldmatrix.sync.aligned.m8n8.x4.shared.b16 {%0,%1,%2,%3}, [%4];"
                 : "=r"(r[0]), "=r"(r[1]), "=r"(r[2]), "=r"(r[3]) : "r"(addr));
}
__device__ __forceinline__ void ldm_x4t(uint32_t* r, uint32_t addr) {
    asm volatile("ldmatrix.sync.aligned.m8n8.x4.trans.shared.b16 {%0,%1,%2,%3}, [%4];"
                 : "=r"(r[0]), "=r"(r[1]), "=r"(r[2]), "=r"(r[3]) : "r"(addr));
}
__device__ __forceinline__ void mma_f16(float* c, const uint32_t* a, const uint32_t* b) {
    asm volatile(
        "mma.sync.aligned.m16n8k16.row.col.f32.f16.f16.f32 "
        "{%0,%1,%2,%3}, {%4,%5,%6,%7}, {%8,%9}, {%0,%1,%2,%3};"
        : "+f"(c[0]), "+f"(c[1]), "+f"(c[2]), "+f"(c[3])
        : "r"(a[0]), "r"(a[1]), "r"(a[2]), "r"(a[3]), "r"(b[0]), "r"(b[1]));
}

// ---------------- smem geometry (4-stage rings, R13 tile sizes) ----------------
#define PITCHB 80
#define TILE_B (128 * PITCHB)           // 10240
#define SC_STAGE (2 * TILE_B)           // 20480
#define SC_RS_OFF (4 * SC_STAGE)        // 81920
#define SC_RINV_OFF (SC_RS_OFF + 2048)
#define SC_SMEM (SC_RINV_OFF + 512)     // 84480
#define AV_A_SZ (128 * 80)              // 10240
#define AV_V_SZ (32 * 272)              // 8704
#define AV_STAGE (AV_A_SZ + AV_V_SZ)    // 18944
#define AV_SMEM (4 * AV_STAGE)          // 75776
#define FU_RED_OFF (4 * AV_STAGE)       // 75776
#define FU_SMEM (FU_RED_OFF + 2048)     // 77824

// ---------------- length normalization ----------------
__global__ void k_lens(const unsigned int* __restrict__ x1l,
                       const unsigned int* __restrict__ x2l) {
    __shared__ int is64;
    int t = threadIdx.x;
    if (t == 0) {
        int all0 = 1;
        for (int i = 1; i < 128; i += 2)
            if (x2l[i] != 0u) { all0 = 0; break; }
        is64 = all0;
    }
    __syncthreads();
    if (t < 32)  g_qlen[t] = (int)(is64 ? x1l[2 * t] : x1l[t]);
    if (t < 128) g_klen[t] = (int)(is64 ? x2l[2 * t] : x2l[t]);
}

// ---------------- per-pair V colmeans + fused x2 -> fp16 conversion ----------------
__global__ void k_vmean(const float* __restrict__ x2) {
    int p = blockIdx.x, e = threadIdx.x;
    const float* base = x2 + (size_t)p * 262144 + e;
    __half* kh = g_kh + (size_t)p * 262144 + e;
    float s0 = 0.f, s1 = 0.f, s2 = 0.f, s3 = 0.f;
    for (int k = 0; k < 512; k += 4) {
        float v0 = base[(k + 0) * 512];
        float v1 = base[(k + 1) * 512];
        float v2 = base[(k + 2) * 512];
        float v3 = base[(k + 3) * 512];
        s0 += v0; s1 += v1; s2 += v2; s3 += v3;
        kh[(k + 0) * 512] = __float2half(v0);
        kh[(k + 1) * 512] = __float2half(v1);
        kh[(k + 2) * 512] = __float2half(v2);
        kh[(k + 3) * 512] = __float2half(v3);
    }
    g_vmean[p * 512 + e] = (s0 + s1 + s2 + s3) * (1.f / 512.f);
}

// ---------------- fp32 -> fp16 (single) ----------------
__global__ void k_cvt1(const float* __restrict__ src, __half* __restrict__ hi, int n4) {
    int i = blockIdx.x * blockDim.x + threadIdx.x;
    if (i >= n4) return;
    float4 v = ((const float4*)src)[i];
    ((__half2*)hi)[2 * i] = __floats2half2_rn(v.x, v.y);
    ((__half2*)hi)[2 * i + 1] = __floats2half2_rn(v.z, v.w);
}

// ---------------- scores: Q@K^T (1-term fp16), masked exp -> fp16 + fp32 attn -----
__global__ __launch_bounds__(256, 2) void k_scores_mma(float* __restrict__ attn) {
    extern __shared__ char smem[];
    uint32_t sb = smem_u32(smem);
    int t = threadIdx.x, lane = t & 31, wid = t >> 5;
    int wm = wid >> 2, wn = wid & 3;
    int p = blockIdx.y, x1i = p & 31;
    int qt = blockIdx.x, q0 = qt * 128;
    int qlen = g_qlen[x1i], klen = g_klen[p];

    bool all_masked = (q0 >= qlen) || (klen == 0);
    int n_nt = all_masked ? 0 : min(4, (klen + 127) >> 7);
    int n_stages = n_nt * 16;

    const char* Qh = (const char*)(g_qh + (size_t)x1i * 262144);
    const char* Kh = (const char*)(g_kh + (size_t)p * 262144);

    float acc[4][4][4];
#pragma unroll
    for (int a = 0; a < 4; a++)
#pragma unroll
        for (int b = 0; b < 4; b++)
#pragma unroll
            for (int c = 0; c < 4; c++) acc[a][b][c] = 0.f;
    float rsum[4][2];
#pragma unroll
    for (int a = 0; a < 4; a++) rsum[a][0] = rsum[a][1] = 0.f;

    auto load_stage = [&](int s) {
        int nt = s >> 4, ec = s & 15;
        uint32_t bb = sb + (s & 3) * SC_STAGE;
#pragma unroll
        for (int h = 0; h < 2; h++) {
            int idx = h * 256 + t;
            int row = idx >> 2, q = (idx & 3) * 16;
            uint32_t dst = row * PITCHB + q;
            size_t asrc = (size_t)(q0 + row) * 1024 + ec * 64 + q;
            size_t bsrc = (size_t)(nt * 128 + row) * 1024 + ec * 64 + q;
            cp_async16(bb + dst, Qh + asrc);
            cp_async16(bb + TILE_B + dst, Kh + bsrc);
        }
    };

    if (n_stages > 0) {
        load_stage(0);
        CP_COMMIT();
        if (n_stages > 1) load_stage(1);
        CP_COMMIT();
        if (n_stages > 2) load_stage(2);
        CP_COMMIT();
    }

    __half2* AH = (__half2*)(g_ah + (size_t)p * 262144);

    for (int s = 0; s < n_stages; s++) {
        CP_WAIT(2);
        __syncthreads();
        if (s + 3 < n_stages) load_stage(s + 3);
        CP_COMMIT();
        uint32_t bb = sb + (s & 3) * SC_STAGE;
#pragma unroll
        for (int kk = 0; kk < 2; kk++) {
            uint32_t aBase = bb + (wm * 64 + (lane & 15)) * PITCHB + (lane >> 4) * 16 +
                             kk * 32;
            uint32_t aHi[4][4];
#pragma unroll
            for (int mt = 0; mt < 4; mt++)
                ldm_x4(aHi[mt], aBase + mt * 16 * PITCHB);
            uint32_t bBase = bb + TILE_B +
                             (wn * 32 + ((lane >> 4) & 1) * 8 + (lane & 7)) * PITCHB +
                             ((lane >> 3) & 1) * 16 + kk * 32;
#pragma unroll
            for (int pr = 0; pr < 2; pr++) {
                uint32_t bH[4];
                ldm_x4(bH, bBase + pr * 16 * PITCHB);
#pragma unroll
                for (int mt = 0; mt < 4; mt++)
#pragma unroll
                    for (int n2 = 0; n2 < 2; n2++)
                        mma_f16(acc[mt][pr * 2 + n2], aHi[mt], bH + 2 * n2);
            }
        }
        if ((s & 15) == 15) {
            int nt = s >> 4;
            int nb = nt * 128 + wn * 32;
#pragma unroll
            for (int mt = 0; mt < 4; mt++) {
                int r0 = q0 + wm * 64 + mt * 16 + (lane >> 2);
                bool fm0 = (r0 >= qlen);
                bool fm1 = ((r0 + 8) >= qlen);
#pragma unroll
                for (int ntl = 0; ntl < 4; ntl++) {
                    int col = nb + ntl * 8 + (lane & 3) * 2;
                    float* cc = acc[mt][ntl];
                    float e0 = fm0 ? 1.f : ((col < klen) ? __expf(cc[0] * SCALE_F) : 0.f);
                    float e1 = fm0 ? 1.f : ((col + 1 < klen) ? __expf(cc[1] * SCALE_F) : 0.f);
                    float e2 = fm1 ? 1.f : ((col < klen) ? __expf(cc[2] * SCALE_F) : 0.f);
                    float e3 = fm1 ? 1.f : ((col + 1 < klen) ? __expf(cc[3] * SCALE_F) : 0.f);
                    rsum[mt][0] += e0 + e1;
                    rsum[mt][1] += e2 + e3;
                    AH[((size_t)r0 * 512 + col) >> 1] = __floats2half2_rn(e0, e1);
                    AH[((size_t)(r0 + 8) * 512 + col) >> 1] = __floats2half2_rn(e2, e3);
                    cc[0] = cc[1] = cc[2] = cc[3] = 0.f;
                }
            }
        }
    }

    // fill skipped 128-col blocks: masked rows -> exp 1, live rows -> 0
    {
        __half* AHB = g_ah + (size_t)p * 262144;
        const uint32_t ONE2 = 0x3C003C00u;
        uint4 vone = make_uint4(ONE2, ONE2, ONE2, ONE2);
        uint4 vzer = make_uint4(0u, 0u, 0u, 0u);
        for (int nt = n_nt; nt < 4; nt++) {
            for (int i = t; i < 2048; i += 256) {
                int row = i >> 4, c8 = (i & 15) * 8;
                bool mr = all_masked || ((q0 + row) >= qlen);
                size_t o = (size_t)(q0 + row) * 512 + nt * 128 + c8;
                *(uint4*)(AHB + o) = mr ? vone : vzer;
            }
        }
    }

    __syncthreads();
    float* rs = (float*)(smem + SC_RS_OFF);
    float* rinv = (float*)(smem + SC_RINV_OFF);
#pragma unroll
    for (int mt = 0; mt < 4; mt++)
#pragma unroll
        for (int ri = 0; ri < 2; ri++) {
            float v = rsum[mt][ri];
            v += __shfl_xor_sync(0xffffffffu, v, 1);
            v += __shfl_xor_sync(0xffffffffu, v, 2);
            if ((lane & 3) == 0)
                rs[(wm * 64 + mt * 16 + ri * 8 + (lane >> 2)) * 4 + wn] = v;
        }
    __syncthreads();
    if (t < 128) {
        float s = rs[t * 4] + rs[t * 4 + 1] + rs[t * 4 + 2] + rs[t * 4 + 3];
        bool mr = all_masked || ((q0 + t) >= qlen);
        s += (float)(4 - n_nt) * 128.f * (mr ? 1.f : 0.f);
        g_rowsum[p * 512 + q0 + t] = s;
        rinv[t] = s > 0.f ? 1.f / s : 0.f;
    }
    __syncthreads();

    // normalize tail: fp32 attn from just-written exp (L2-hot) + rowsum
    {
        const __half2* AHB = (const __half2*)(g_ah + (size_t)p * 262144);
        float* AT = attn + (size_t)p * 262144;
        for (int i = t; i < 128 * 128; i += 256) {
            int row = i >> 7, c4 = (i & 127) * 4;
            float inv = rinv[row];
            size_t o = (size_t)(q0 + row) * 512 + c4;
            float2 f0 = __half22float2(AHB[o >> 1]);
            float2 f1 = __half22float2(AHB[(o >> 1) + 1]);
            float4 v;
            v.x = f0.x * inv;
            v.y = f0.y * inv;
            v.z = f1.x * inv;
            v.w = f1.y * inv;
            *(float4*)(AT + o) = v;
        }
    }
}

// ---------------- x1_att = exp @ V / rowsum (1-term fp16); emits cat fp16 ----------
__global__ __launch_bounds__(256, 2) void k_av_mma(const float* __restrict__ x1) {
    extern __shared__ char smem[];
    uint32_t sb = smem_u32(smem);
    int t = threadIdx.x, lane = t & 31, wid = t >> 5;
    int wm = wid >> 2, wn = wid & 3;
    int p = blockIdx.z, x1i = p & 31;
    int q0 = blockIdx.y * 128, e0 = blockIdx.x * 128;
    int qlen = g_qlen[x1i], klen = g_klen[p];

    bool all_masked = (q0 >= qlen) || (klen == 0);
    int n_stage = all_masked ? 0 : min(16, (klen + 31) >> 5);

    const char* Ah = (const char*)(g_ah + (size_t)p * 262144);
    const char* Vh = (const char*)(g_kh + (size_t)p * 262144);

    float acc[4][4][4];
#pragma unroll
    for (int a = 0; a < 4; a++)
#pragma unroll
        for (int b = 0; b < 4; b++)
#pragma unroll
            for (int c = 0; c < 4; c++) acc[a][b][c] = 0.f;

    auto load_stage = [&](int s) {
        uint32_t bb = sb + (s & 3) * AV_STAGE;
#pragma unroll
        for (int h = 0; h < 2; h++) {
            int idx = h * 256 + t;
            int row = idx >> 2, ch = idx & 3;
            size_t off = (size_t)(q0 + row) * 1024 + s * 64 + ch * 16;
            cp_async16(bb + row * 80 + ch * 16, Ah + off);
        }
#pragma unroll
        for (int h = 0; h < 2; h++) {
            int idx = h * 256 + t;
            int row = idx >> 4, ch = idx & 15;
            size_t off = (size_t)(s * 32 + row) * 1024 + e0 * 2 + ch * 16;
            cp_async16(bb + AV_A_SZ + row * 272 + ch * 16, Vh + off);
        }
    };

    if (n_stage > 0) {
        load_stage(0);
        CP_COMMIT();
        if (n_stage > 1) load_stage(1);
        CP_COMMIT();
        if (n_stage > 2) load_stage(2);
        CP_COMMIT();
    }

    for (int s = 0; s < n_stage; s++) {
        CP_WAIT(2);
        __syncthreads();
        if (s + 3 < n_stage) load_stage(s + 3);
        CP_COMMIT();
        uint32_t bb = sb + (s & 3) * AV_STAGE;
#pragma unroll
        for (int kk = 0; kk < 2; kk++) {
            uint32_t aBase = bb + (wm * 64 + (lane & 15)) * 80 + (lane >> 4) * 16 + kk * 32;
            uint32_t aHi[4][4];
#pragma unroll
            for (int mt = 0; mt < 4; mt++)
                ldm_x4(aHi[mt], aBase + mt * 16 * 80);
            uint32_t bBase = bb + AV_A_SZ + (kk * 16 + (lane & 15)) * 272 + wn * 64 +
                             ((lane >> 4) & 1) * 16;
#pragma unroll
            for (int pr = 0; pr < 2; pr++) {
                uint32_t bH[4];
                ldm_x4t(bH, bBase + pr * 32);
#pragma unroll
                for (int mt = 0; mt < 4; mt++)
#pragma unroll
                    for (int n2 = 0; n2 < 2; n2++)
                        mma_f16(acc[mt][pr * 2 + n2], aHi[mt], bH + 2 * n2);
            }
        }
    }

    // epilogue: xa = acc/rowsum (masked rows: colmean V) -> (x1-xa, x1*xa) fp16
    const float* X1 = x1 + (size_t)x1i * 262144;
    const float* VM = g_vmean + p * 512;
    __half2* Sh = (__half2*)(g_sh + (size_t)p * 262144);
    __half2* Mh = (__half2*)(g_mh + (size_t)p * 262144);
#pragma unroll
    for (int mt = 0; mt < 4; mt++) {
#pragma unroll
        for (int hh = 0; hh < 2; hh++) {
            int r = q0 + wm * 64 + mt * 16 + (lane >> 2) + hh * 8;
            bool mr = all_masked || (r >= qlen);
            float inv = 0.f;
            if (!mr) inv = 1.f / g_rowsum[p * 512 + r];
#pragma unroll
            for (int ntl = 0; ntl < 4; ntl++) {
                float* cc = acc[mt][ntl];
                int c = e0 + wn * 32 + ntl * 8 + (lane & 3) * 2;
                float2 u = *(const float2*)(X1 + (size_t)r * 512 + c);
                float xa0, xa1;
                if (mr) {
                    float2 vm = *(const float2*)(VM + c);
                    xa0 = vm.x;
                    xa1 = vm.y;
                } else {
                    xa0 = cc[hh * 2] * inv;
                    xa1 = cc[hh * 2 + 1] * inv;
                }
                size_t o = ((size_t)r * 512 + c) >> 1;
                Sh[o] = __floats2half2_rn(u.x - xa0, u.y - xa1);
                Mh[o] = __floats2half2_rn(u.x * xa0, u.y * xa1);
            }
        }
    }
}

// ---------------- fusion GEMM (1-term fp16) + bias/relu + partial pooling ----------
__global__ __launch_bounds__(256, 2) void k_fusion_mma(const float* __restrict__ fb) {
    extern __shared__ char smem[];
    uint32_t sb = smem_u32(smem);
    int t = threadIdx.x, lane = t & 31, wid = t >> 5;
    int wm = wid >> 2, wn = wid & 3;
    int p = blockIdx.z;
    int qt = blockIdx.y, q0 = qt * 128, e0 = blockIdx.x * 128;

    const char* Sh = (const char*)(g_sh + (size_t)p * 262144);
    const char* Mh = (const char*)(g_mh + (size_t)p * 262144);
    const char* Wh = (const char*)g_fwh;

    float acc[4][4][4];
#pragma unroll
    for (int a = 0; a < 4; a++)
#pragma unroll
        for (int b = 0; b < 4; b++)
#pragma unroll
            for (int c = 0; c < 4; c++) acc[a][b][c] = 0.f;

    auto load_stage = [&](int s) {
        uint32_t bb = sb + (s & 3) * AV_STAGE;
        const char* ah = (s < 16) ? Sh : Mh;
        int kc = (s & 15) * 64;
#pragma unroll
        for (int h = 0; h < 2; h++) {
            int idx = h * 256 + t;
            int row = idx >> 2, ch = idx & 3;
            size_t off = (size_t)(q0 + row) * 1024 + kc + ch * 16;
            cp_async16(bb + row * 80 + ch * 16, ah + off);
        }
#pragma unroll
        for (int h = 0; h < 2; h++) {
            int idx = h * 256 + t;
            int row = idx >> 4, ch = idx & 15;
            size_t off = (size_t)(s * 32 + row) * 1024 + e0 * 2 + ch * 16;
            cp_async16(bb + AV_A_SZ + row * 272 + ch * 16, Wh + off);
        }
    };

    load_stage(0);
    CP_COMMIT();
    load_stage(1);
    CP_COMMIT();
    load_stage(2);
    CP_COMMIT();

    for (int s = 0; s < 32; s++) {
        CP_WAIT(2);
        __syncthreads();
        if (s + 3 < 32) load_stage(s + 3);
        CP_COMMIT();
        uint32_t bb = sb + (s & 3) * AV_STAGE;
#pragma unroll
        for (int kk = 0; kk < 2; kk++) {
            uint32_t aBase = bb + (wm * 64 + (lane & 15)) * 80 + (lane >> 4) * 16 + kk * 32;
            uint32_t aHi[4][4];
#pragma unroll
            for (int mt = 0; mt < 4; mt++)
                ldm_x4(aHi[mt], aBase + mt * 16 * 80);
            uint32_t bBase = bb + AV_A_SZ + (kk * 16 + (lane & 15)) * 272 + wn * 64 +
                             ((lane >> 4) & 1) * 16;
#pragma unroll
            for (int pr = 0; pr < 2; pr++) {
                uint32_t bH[4];
                ldm_x4t(bH, bBase + pr * 32);
#pragma unroll
                for (int mt = 0; mt < 4; mt++)
#pragma unroll
                    for (int n2 = 0; n2 < 2; n2++)
                        mma_f16(acc[mt][pr * 2 + n2], aHi[mt], bH + 2 * n2);
            }
        }
    }

    // bias + relu + pool over this block's 128 rows
    float psum[4][2], pmax[4][2];
#pragma unroll
    for (int ntl = 0; ntl < 4; ntl++) {
        psum[ntl][0] = psum[ntl][1] = 0.f;
        pmax[ntl][0] = pmax[ntl][1] = 0.f;
    }
#pragma unroll
    for (int ntl = 0; ntl < 4; ntl++) {
        int c = e0 + wn * 32 + ntl * 8 + (lane & 3) * 2;
        float b0 = fb[c], b1 = fb[c + 1];
#pragma unroll
        for (int mt = 0; mt < 4; mt++) {
            float* cc = acc[mt][ntl];
            float v0 = fmaxf(cc[0] + b0, 0.f);
            float v1 = fmaxf(cc[1] + b1, 0.f);
            float v2 = fmaxf(cc[2] + b0, 0.f);
            float v3 = fmaxf(cc[3] + b1, 0.f);
            psum[ntl][0] += v0 + v2;
            psum[ntl][1] += v1 + v3;
            pmax[ntl][0] = fmaxf(pmax[ntl][0], fmaxf(v0, v2));
            pmax[ntl][1] = fmaxf(pmax[ntl][1], fmaxf(v1, v3));
        }
    }
    __syncthreads();
    float* redS = (float*)(smem + FU_RED_OFF);
    float* redM = redS + 256;
#pragma unroll
    for (int ntl = 0; ntl < 4; ntl++)
#pragma unroll
        for (int j = 0; j < 2; j++) {
            float s = psum[ntl][j], m = pmax[ntl][j];
            s += __shfl_xor_sync(0xffffffffu, s, 4);
            s += __shfl_xor_sync(0xffffffffu, s, 8);
            s += __shfl_xor_sync(0xffffffffu, s, 16);
            m = fmaxf(m, __shfl_xor_sync(0xffffffffu, m, 4));
            m = fmaxf(m, __shfl_xor_sync(0xffffffffu, m, 8));
            m = fmaxf(m, __shfl_xor_sync(0xffffffffu, m, 16));
            if (lane < 4) {
                int col = wn * 32 + ntl * 8 + lane * 2 + j;
                redS[wm * 128 + col] = s;
                redM[wm * 128 + col] = m;
            }
        }
    __syncthreads();
    if (t < 128) {
        float s = redS[t] + redS[128 + t];
        float m = fmaxf(redM[t], redM[128 + t]);
        int idx = (p * 4 + qt) * 512 + e0 + t;
        g_psum[idx] = s;
        g_pmax[idx] = m;
    }
}

// ---------------- pool finalize ----------------
__global__ void k_pool(void) {
    int p = blockIdx.x, e = threadIdx.x;
    float s = 0.f, m = 0.f;
#pragma unroll
    for (int qt = 0; qt < 4; qt++) {
        int idx = (p * 4 + qt) * 512 + e;
        s += g_psum[idx];
        m = fmaxf(m, g_pmax[idx]);
    }
    int base = (p >> 2) * 4096 + (p & 3) * 512 + e;
    g_pooled[base] = s * (1.0f / 512.0f);
    g_pooled[base + 2048] = m;
}

// ---------------- out GEMM: k-split partials ----------------
__global__ __launch_bounds__(256) void k_out_part(const float* __restrict__ ow) {
    __shared__ float sp[512];
    int b = blockIdx.x, ks = blockIdx.y, t = threadIdx.x;
    for (int i = t; i < 512; i += 256) sp[i] = g_pooled[b * 4096 + ks * 512 + i];
    __syncthreads();
    int col = t * 4;
    float4 acc = make_float4(0.f, 0.f, 0.f, 0.f);
#pragma unroll 8
    for (int c = 0; c < 512; c++) {
        float pv = sp[c];
        float4 w = *(const float4*)(ow + (size_t)(ks * 512 + c) * 1024 + col);
        acc.x += pv * w.x;
        acc.y += pv * w.y;
        acc.z += pv * w.z;
        acc.w += pv * w.w;
    }
    *(float4*)(g_opart + ((size_t)ks * 32 + b) * 1024 + col) = acc;
}

// ---------------- out finalize: fixed-order sum + bias + relu ----------------
__global__ __launch_bounds__(256) void k_out_fin(const float* __restrict__ ob,
                                                 float* __restrict__ outp) {
    int b = blockIdx.x, col = threadIdx.x * 4;
    float4 acc = *(const float4*)(ob + col);
#pragma unroll
    for (int ks = 0; ks < 8; ks++) {
        float4 v = *(const float4*)(g_opart + ((size_t)ks * 32 + b) * 1024 + col);
        acc.x += v.x;
        acc.y += v.y;
        acc.z += v.z;
        acc.w += v.w;
    }
    acc.x = fmaxf(acc.x, 0.f);
    acc.y = fmaxf(acc.y, 0.f);
    acc.z = fmaxf(acc.z, 0.f);
    acc.w = fmaxf(acc.w, 0.f);
    *(float4*)(outp + b * 1024 + col) = acc;
}

extern "C" void kernel_launch(void* const* d_in, const int* in_sizes, int n_in,
                              void* d_out, int out_size) {
    const float* x1 = (const float*)d_in[0];
    const float* x2 = (const float*)d_in[1];
    const unsigned int* x1_len = (const unsigned int*)d_in[2];
    const unsigned int* x2_len = (const unsigned int*)d_in[3];
    const float* fw = (const float*)d_in[4];
    const float* fb = (const float*)d_in[5];
    const float* ow = (const float*)d_in[6];
    const float* ob = (const float*)d_in[7];

    float* outp = (float*)d_out;
    float* attn;
    if (out_size >= OUT_ELEMS + ATTN_ELEMS) {
        attn = outp + OUT_ELEMS;
    } else if (out_size >= ATTN_ELEMS) {
        attn = outp;
        void* dp = nullptr;
        cudaGetSymbolAddress(&dp, g_out_dummy);
        outp = (float*)dp;
    } else {
        void* dp = nullptr;
        cudaGetSymbolAddress(&dp, g_attn_scratch);
        attn = (float*)dp;
    }

    void *qh, *fwh;
    cudaGetSymbolAddress(&qh, g_qh);
    cudaGetSymbolAddress(&fwh, g_fwh);

    cudaFuncSetAttribute(k_scores_mma, cudaFuncAttributeMaxDynamicSharedMemorySize, SC_SMEM);
    cudaFuncSetAttribute(k_av_mma, cudaFuncAttributeMaxDynamicSharedMemorySize, AV_SMEM);
    cudaFuncSetAttribute(k_fusion_mma, cudaFuncAttributeMaxDynamicSharedMemorySize, FU_SMEM);

    k_lens<<<1, 128>>>(x1_len, x2_len);
    k_vmean<<<NPAIR, 512>>>(x2);
    k_cvt1<<<8192, 256>>>(x1, (__half*)qh, 2097152);
    k_cvt1<<<512, 256>>>(fw, (__half*)fwh, 131072);
    k_scores_mma<<<dim3(4, NPAIR), 256, SC_SMEM>>>(attn);
    k_av_mma<<<dim3(4, 4, NPAIR), 256, AV_SMEM>>>(x1);
    k_fusion_mma<<<dim3(4, 4, NPAIR), 256, FU_SMEM>>>(fb);
    k_pool<<<NPAIR, 512>>>();
    k_out_part<<<dim3(NB, 8), 256>>>(ow);
    k_out_fin<<<NB, 256>>>(ob, outp);
}

// round 16
// speedup vs baseline: 1.0780x; 1.0690x over previous
#include <cuda_runtime.h>
#include <cuda_fp16.h>
#include <cstdint>

#define CL 512
#define CE 512
#define NPAIR 128
#define NB 32
#define ATTN_ELEMS (NPAIR * CL * CL)
#define OUT_ELEMS (NB * 1024)
#define SCALE_F 0.044194173824159216f

// ---------------- scratch (device globals; alloc-free rule) ----------------
__device__ float g_attn_scratch[ATTN_ELEMS];
__device__ float g_out_dummy[OUT_ELEMS];
__device__ float g_rowsum[NPAIR * CL];
__device__ float g_psum[4 * NPAIR * CL];
__device__ float g_pmax[4 * NPAIR * CL];
__device__ float g_vmean[NPAIR * CE];
__device__ float g_vpart[4 * NPAIR * CE];
__device__ float g_opart[8 * NB * 1024];
__device__ int g_qlen[32];
__device__ int g_klen[128];
__device__ __half g_qh[NB * CL * CE];     // x1 fp16
__device__ __half g_kh[NPAIR * CL * CE];  // x2 fp16
__device__ __half g_ah[NPAIR * CL * CL];  // UNNORMALIZED exp fp16
__device__ __half g_sh[NPAIR * CL * CE];  // x1 - xa fp16
__device__ __half g_mh[NPAIR * CL * CE];  // x1 * xa fp16
__device__ __half g_fwh[1024 * 512];      // fusion_w fp16

// ---------------- PTX helpers ----------------
__device__ __forceinline__ uint32_t smem_u32(const void* p) {
    uint32_t a;
    asm("{ .reg .u64 t; cvta.to.shared.u64 t, %1; cvt.u32.u64 %0, t; }" : "=r"(a) : "l"(p));
    return a;
}
__device__ __forceinline__ void cp_async16(uint32_t dst, const void* src) {
    asm volatile("cp.async.ca.shared.global [%0], [%1], 16;" :: "r"(dst), "l"(src));
}
#define CP_COMMIT() asm volatile("cp.async.commit_group;" ::: "memory")
#define CP_WAIT(n)  asm volatile("cp.async.wait_group %0;" :: "n"(n) : "memory")

__device__ __forceinline__ void ldm_x4(uint32_t* r, uint32_t addr) {
    asm volatile("ldmatrix.sync.aligned.m8n8.x4.shared.b16 {%0,%1,%2,%3}, [%4];"
                 : "=r"(r[0]), "=r"(r[1]), "=r"(r[2]), "=r"(r[3]) : "r"(addr));
}
__device__ __forceinline__ void ldm_x4t(uint32_t* r, uint32_t addr) {
    asm volatile("ldmatrix.sync.aligned.m8n8.x4.trans.shared.b16 {%0,%1,%2,%3}, [%4];"
                 : "=r"(r[0]), "=r"(r[1]), "=r"(r[2]), "=r"(r[3]) : "r"(addr));
}
__device__ __forceinline__ void mma_f16(float* c, const uint32_t* a, const uint32_t* b) {
    asm volatile(
        "mma.sync.aligned.m16n8k16.row.col.f32.f16.f16.f32 "
        "{%0,%1,%2,%3}, {%4,%5,%6,%7}, {%8,%9}, {%0,%1,%2,%3};"
        : "+f"(c[0]), "+f"(c[1]), "+f"(c[2]), "+f"(c[3])
        : "r"(a[0]), "r"(a[1]), "r"(a[2]), "r"(a[3]), "r"(b[0]), "r"(b[1]));
}

// ---------------- smem geometry (R13: 3-stage rings, 128x128 tiles) ----------------
#define PITCHB 80
#define TILE_B (128 * PITCHB)           // 10240
#define SC_STAGE (2 * TILE_B)           // 20480
#define SC_RS_OFF (3 * SC_STAGE)        // 61440
#define SC_RINV_OFF (SC_RS_OFF + 2048)
#define SC_SMEM (SC_RINV_OFF + 512)     // 63a ~64000
#define AV_A_SZ (128 * 80)              // 10240
#define AV_V_SZ (32 * 272)              // 8704
#define AV_STAGE (AV_A_SZ + AV_V_SZ)    // 18944
#define AV_SMEM (3 * AV_STAGE)          // 56832
#define FU_RED_OFF (3 * AV_STAGE)       // 56832
#define FU_SMEM (FU_RED_OFF + 2048)     // 58880

// ---------------- length normalization ----------------
__global__ void k_lens(const unsigned int* __restrict__ x1l,
                       const unsigned int* __restrict__ x2l) {
    __shared__ int is64;
    int t = threadIdx.x;
    if (t == 0) {
        int all0 = 1;
        for (int i = 1; i < 128; i += 2)
            if (x2l[i] != 0u) { all0 = 0; break; }
        is64 = all0;
    }
    __syncthreads();
    if (t < 32)  g_qlen[t] = (int)(is64 ? x1l[2 * t] : x1l[t]);
    if (t < 128) g_klen[t] = (int)(is64 ? x2l[2 * t] : x2l[t]);
}

// ---------------- V colmean partials + fused x2 -> fp16 conversion (k-split) -------
__global__ void k_vmean_part(const float* __restrict__ x2) {
    int p = blockIdx.y, kc = blockIdx.x * 128, e = threadIdx.x;
    const float* base = x2 + (size_t)p * 262144 + (size_t)kc * 512 + e;
    __half* kh = g_kh + (size_t)p * 262144 + (size_t)kc * 512 + e;
    float s0 = 0.f, s1 = 0.f, s2 = 0.f, s3 = 0.f;
    for (int k = 0; k < 128; k += 4) {
        float v0 = base[(k + 0) * 512];
        float v1 = base[(k + 1) * 512];
        float v2 = base[(k + 2) * 512];
        float v3 = base[(k + 3) * 512];
        s0 += v0; s1 += v1; s2 += v2; s3 += v3;
        kh[(k + 0) * 512] = __float2half(v0);
        kh[(k + 1) * 512] = __float2half(v1);
        kh[(k + 2) * 512] = __float2half(v2);
        kh[(k + 3) * 512] = __float2half(v3);
    }
    g_vpart[(p * 4 + blockIdx.x) * 512 + e] = (s0 + s1) + (s2 + s3);
}

__global__ void k_vmean_fin(void) {
    int p = blockIdx.x, e = threadIdx.x;
    float s = g_vpart[(p * 4 + 0) * 512 + e] + g_vpart[(p * 4 + 1) * 512 + e] +
              g_vpart[(p * 4 + 2) * 512 + e] + g_vpart[(p * 4 + 3) * 512 + e];
    g_vmean[p * 512 + e] = s * (1.f / 512.f);
}

// ---------------- fp32 -> fp16 (single) ----------------
__global__ void k_cvt1(const float* __restrict__ src, __half* __restrict__ hi, int n4) {
    int i = blockIdx.x * blockDim.x + threadIdx.x;
    if (i >= n4) return;
    float4 v = ((const float4*)src)[i];
    ((__half2*)hi)[2 * i] = __floats2half2_rn(v.x, v.y);
    ((__half2*)hi)[2 * i + 1] = __floats2half2_rn(v.z, v.w);
}

// ---------------- scores: Q@K^T (1-term fp16), masked exp -> fp16 + fp32 attn -----
__global__ __launch_bounds__(256, 2) void k_scores_mma(float* __restrict__ attn) {
    extern __shared__ char smem[];
    uint32_t sb = smem_u32(smem);
    int t = threadIdx.x, lane = t & 31, wid = t >> 5;
    int wm = wid >> 2, wn = wid & 3;
    int p = blockIdx.y, x1i = p & 31;
    int qt = blockIdx.x, q0 = qt * 128;
    int qlen = g_qlen[x1i], klen = g_klen[p];

    bool all_masked = (q0 >= qlen) || (klen == 0);
    int n_nt = all_masked ? 0 : min(4, (klen + 127) >> 7);
    int n_stages = n_nt * 16;

    const char* Qh = (const char*)(g_qh + (size_t)x1i * 262144);
    const char* Kh = (const char*)(g_kh + (size_t)p * 262144);

    float acc[4][4][4];
#pragma unroll
    for (int a = 0; a < 4; a++)
#pragma unroll
        for (int b = 0; b < 4; b++)
#pragma unroll
            for (int c = 0; c < 4; c++) acc[a][b][c] = 0.f;
    float rsum[4][2];
#pragma unroll
    for (int a = 0; a < 4; a++) rsum[a][0] = rsum[a][1] = 0.f;

    auto load_stage = [&](int s) {
        int nt = s >> 4, ec = s & 15;
        uint32_t bb = sb + (s % 3) * SC_STAGE;
#pragma unroll
        for (int h = 0; h < 2; h++) {
            int idx = h * 256 + t;
            int row = idx >> 2, q = (idx & 3) * 16;
            uint32_t dst = row * PITCHB + q;
            size_t asrc = (size_t)(q0 + row) * 1024 + ec * 64 + q;
            size_t bsrc = (size_t)(nt * 128 + row) * 1024 + ec * 64 + q;
            cp_async16(bb + dst, Qh + asrc);
            cp_async16(bb + TILE_B + dst, Kh + bsrc);
        }
    };

    if (n_stages > 0) {
        load_stage(0);
        CP_COMMIT();
        if (n_stages > 1) load_stage(1);
        CP_COMMIT();
    }

    __half2* AH = (__half2*)(g_ah + (size_t)p * 262144);

    for (int s = 0; s < n_stages; s++) {
        CP_WAIT(1);
        __syncthreads();
        if (s + 2 < n_stages) load_stage(s + 2);
        CP_COMMIT();
        uint32_t bb = sb + (s % 3) * SC_STAGE;
#pragma unroll
        for (int kk = 0; kk < 2; kk++) {
            uint32_t aBase = bb + (wm * 64 + (lane & 15)) * PITCHB + (lane >> 4) * 16 +
                             kk * 32;
            uint32_t aHi[4][4];
#pragma unroll
            for (int mt = 0; mt < 4; mt++)
                ldm_x4(aHi[mt], aBase + mt * 16 * PITCHB);
            uint32_t bBase = bb + TILE_B +
                             (wn * 32 + ((lane >> 4) & 1) * 8 + (lane & 7)) * PITCHB +
                             ((lane >> 3) & 1) * 16 + kk * 32;
#pragma unroll
            for (int pr = 0; pr < 2; pr++) {
                uint32_t bH[4];
                ldm_x4(bH, bBase + pr * 16 * PITCHB);
#pragma unroll
                for (int mt = 0; mt < 4; mt++)
#pragma unroll
                    for (int n2 = 0; n2 < 2; n2++)
                        mma_f16(acc[mt][pr * 2 + n2], aHi[mt], bH + 2 * n2);
            }
        }
        if ((s & 15) == 15) {
            int nt = s >> 4;
            int nb = nt * 128 + wn * 32;
#pragma unroll
            for (int mt = 0; mt < 4; mt++) {
                int r0 = q0 + wm * 64 + mt * 16 + (lane >> 2);
                bool fm0 = (r0 >= qlen);
                bool fm1 = ((r0 + 8) >= qlen);
#pragma unroll
                for (int ntl = 0; ntl < 4; ntl++) {
                    int col = nb + ntl * 8 + (lane & 3) * 2;
                    float* cc = acc[mt][ntl];
                    float e0 = fm0 ? 1.f : ((col < klen) ? __expf(cc[0] * SCALE_F) : 0.f);
                    float e1 = fm0 ? 1.f : ((col + 1 < klen) ? __expf(cc[1] * SCALE_F) : 0.f);
                    float e2 = fm1 ? 1.f : ((col < klen) ? __expf(cc[2] * SCALE_F) : 0.f);
                    float e3 = fm1 ? 1.f : ((col + 1 < klen) ? __expf(cc[3] * SCALE_F) : 0.f);
                    rsum[mt][0] += e0 + e1;
                    rsum[mt][1] += e2 + e3;
                    AH[((size_t)r0 * 512 + col) >> 1] = __floats2half2_rn(e0, e1);
                    AH[((size_t)(r0 + 8) * 512 + col) >> 1] = __floats2half2_rn(e2, e3);
                    cc[0] = cc[1] = cc[2] = cc[3] = 0.f;
                }
            }
        }
    }

    // fill skipped 128-col blocks: masked rows -> exp 1, live rows -> 0
    {
        __half* AHB = g_ah + (size_t)p * 262144;
        const uint32_t ONE2 = 0x3C003C00u;
        uint4 vone = make_uint4(ONE2, ONE2, ONE2, ONE2);
        uint4 vzer = make_uint4(0u, 0u, 0u, 0u);
        for (int nt = n_nt; nt < 4; nt++) {
            for (int i = t; i < 2048; i += 256) {
                int row = i >> 4, c8 = (i & 15) * 8;
                bool mr = all_masked || ((q0 + row) >= qlen);
                size_t o = (size_t)(q0 + row) * 512 + nt * 128 + c8;
                *(uint4*)(AHB + o) = mr ? vone : vzer;
            }
        }
    }

    __syncthreads();
    float* rs = (float*)(smem + SC_RS_OFF);
    float* rinv = (float*)(smem + SC_RINV_OFF);
#pragma unroll
    for (int mt = 0; mt < 4; mt++)
#pragma unroll
        for (int ri = 0; ri < 2; ri++) {
            float v = rsum[mt][ri];
            v += __shfl_xor_sync(0xffffffffu, v, 1);
            v += __shfl_xor_sync(0xffffffffu, v, 2);
            if ((lane & 3) == 0)
                rs[(wm * 64 + mt * 16 + ri * 8 + (lane >> 2)) * 4 + wn] = v;
        }
    __syncthreads();
    if (t < 128) {
        float s = rs[t * 4] + rs[t * 4 + 1] + rs[t * 4 + 2] + rs[t * 4 + 3];
        bool mr = all_masked || ((q0 + t) >= qlen);
        s += (float)(4 - n_nt) * 128.f * (mr ? 1.f : 0.f);
        g_rowsum[p * 512 + q0 + t] = s;
        rinv[t] = s > 0.f ? 1.f / s : 0.f;
    }
    __syncthreads();

    // normalize tail: fp32 attn from just-written exp (L2-hot) + rowsum
    {
        const __half2* AHB = (const __half2*)(g_ah + (size_t)p * 262144);
        float* AT = attn + (size_t)p * 262144;
        for (int i = t; i < 128 * 128; i += 256) {
            int row = i >> 7, c4 = (i & 127) * 4;
            float inv = rinv[row];
            size_t o = (size_t)(q0 + row) * 512 + c4;
            float2 f0 = __half22float2(AHB[o >> 1]);
            float2 f1 = __half22float2(AHB[(o >> 1) + 1]);
            float4 v;
            v.x = f0.x * inv;
            v.y = f0.y * inv;
            v.z = f1.x * inv;
            v.w = f1.y * inv;
            *(float4*)(AT + o) = v;
        }
    }
}

// ---------------- x1_att = exp @ V / rowsum (1-term fp16); emits cat fp16 ----------
__global__ __launch_bounds__(256, 2) void k_av_mma(const float* __restrict__ x1) {
    extern __shared__ char smem[];
    uint32_t sb = smem_u32(smem);
    int t = threadIdx.x, lane = t & 31, wid = t >> 5;
    int wm = wid >> 2, wn = wid & 3;
    int p = blockIdx.z, x1i = p & 31;
    int q0 = blockIdx.y * 128, e0 = blockIdx.x * 128;
    int qlen = g_qlen[x1i], klen = g_klen[p];

    bool all_masked = (q0 >= qlen) || (klen == 0);
    int n_stage = all_masked ? 0 : min(16, (klen + 31) >> 5);

    const char* Ah = (const char*)(g_ah + (size_t)p * 262144);
    const char* Vh = (const char*)(g_kh + (size_t)p * 262144);

    float acc[4][4][4];
#pragma unroll
    for (int a = 0; a < 4; a++)
#pragma unroll
        for (int b = 0; b < 4; b++)
#pragma unroll
            for (int c = 0; c < 4; c++) acc[a][b][c] = 0.f;

    auto load_stage = [&](int s) {
        uint32_t bb = sb + (s % 3) * AV_STAGE;
#pragma unroll
        for (int h = 0; h < 2; h++) {
            int idx = h * 256 + t;
            int row = idx >> 2, ch = idx & 3;
            size_t off = (size_t)(q0 + row) * 1024 + s * 64 + ch * 16;
            cp_async16(bb + row * 80 + ch * 16, Ah + off);
        }
#pragma unroll
        for (int h = 0; h < 2; h++) {
            int idx = h * 256 + t;
            int row = idx >> 4, ch = idx & 15;
            size_t off = (size_t)(s * 32 + row) * 1024 + e0 * 2 + ch * 16;
            cp_async16(bb + AV_A_SZ + row * 272 + ch * 16, Vh + off);
        }
    };

    if (n_stage > 0) {
        load_stage(0);
        CP_COMMIT();
        if (n_stage > 1) load_stage(1);
        CP_COMMIT();
    }

    for (int s = 0; s < n_stage; s++) {
        CP_WAIT(1);
        __syncthreads();
        if (s + 2 < n_stage) load_stage(s + 2);
        CP_COMMIT();
        uint32_t bb = sb + (s % 3) * AV_STAGE;
#pragma unroll
        for (int kk = 0; kk < 2; kk++) {
            uint32_t aBase = bb + (wm * 64 + (lane & 15)) * 80 + (lane >> 4) * 16 + kk * 32;
            uint32_t aHi[4][4];
#pragma unroll
            for (int mt = 0; mt < 4; mt++)
                ldm_x4(aHi[mt], aBase + mt * 16 * 80);
            uint32_t bBase = bb + AV_A_SZ + (kk * 16 + (lane & 15)) * 272 + wn * 64 +
                             ((lane >> 4) & 1) * 16;
#pragma unroll
            for (int pr = 0; pr < 2; pr++) {
                uint32_t bH[4];
                ldm_x4t(bH, bBase + pr * 32);
#pragma unroll
                for (int mt = 0; mt < 4; mt++)
#pragma unroll
                    for (int n2 = 0; n2 < 2; n2++)
                        mma_f16(acc[mt][pr * 2 + n2], aHi[mt], bH + 2 * n2);
            }
        }
    }

    // epilogue: xa = acc/rowsum (masked rows: colmean V) -> (x1-xa, x1*xa) fp16
    const float* X1 = x1 + (size_t)x1i * 262144;
    const float* VM = g_vmean + p * 512;
    __half2* Sh = (__half2*)(g_sh + (size_t)p * 262144);
    __half2* Mh = (__half2*)(g_mh + (size_t)p * 262144);
#pragma unroll
    for (int mt = 0; mt < 4; mt++) {
#pragma unroll
        for (int hh = 0; hh < 2; hh++) {
            int r = q0 + wm * 64 + mt * 16 + (lane >> 2) + hh * 8;
            bool mr = all_masked || (r >= qlen);
            float inv = 0.f;
            if (!mr) inv = 1.f / g_rowsum[p * 512 + r];
#pragma unroll
            for (int ntl = 0; ntl < 4; ntl++) {
                float* cc = acc[mt][ntl];
                int c = e0 + wn * 32 + ntl * 8 + (lane & 3) * 2;
                float2 u = *(const float2*)(X1 + (size_t)r * 512 + c);
                float xa0, xa1;
                if (mr) {
                    float2 vm = *(const float2*)(VM + c);
                    xa0 = vm.x;
                    xa1 = vm.y;
                } else {
                    xa0 = cc[hh * 2] * inv;
                    xa1 = cc[hh * 2 + 1] * inv;
                }
                size_t o = ((size_t)r * 512 + c) >> 1;
                Sh[o] = __floats2half2_rn(u.x - xa0, u.y - xa1);
                Mh[o] = __floats2half2_rn(u.x * xa0, u.y * xa1);
            }
        }
    }
}

// ---------------- fusion GEMM (1-term fp16) + bias/relu + partial pooling ----------
__global__ __launch_bounds__(256, 2) void k_fusion_mma(const float* __restrict__ fb) {
    extern __shared__ char smem[];
    uint32_t sb = smem_u32(smem);
    int t = threadIdx.x, lane = t & 31, wid = t >> 5;
    int wm = wid >> 2, wn = wid & 3;
    int p = blockIdx.z;
    int qt = blockIdx.y, q0 = qt * 128, e0 = blockIdx.x * 128;

    const char* Sh = (const char*)(g_sh + (size_t)p * 262144);
    const char* Mh = (const char*)(g_mh + (size_t)p * 262144);
    const char* Wh = (const char*)g_fwh;

    float acc[4][4][4];
#pragma unroll
    for (int a = 0; a < 4; a++)
#pragma unroll
        for (int b = 0; b < 4; b++)
#pragma unroll
            for (int c = 0; c < 4; c++) acc[a][b][c] = 0.f;

    auto load_stage = [&](int s) {
        uint32_t bb = sb + (s % 3) * AV_STAGE;
        const char* ah = (s < 16) ? Sh : Mh;
        int kc = (s & 15) * 64;
#pragma unroll
        for (int h = 0; h < 2; h++) {
            int idx = h * 256 + t;
            int row = idx >> 2, ch = idx & 3;
            size_t off = (size_t)(q0 + row) * 1024 + kc + ch * 16;
            cp_async16(bb + row * 80 + ch * 16, ah + off);
        }
#pragma unroll
        for (int h = 0; h < 2; h++) {
            int idx = h * 256 + t;
            int row = idx >> 4, ch = idx & 15;
            size_t off = (size_t)(s * 32 + row) * 1024 + e0 * 2 + ch * 16;
            cp_async16(bb + AV_A_SZ + row * 272 + ch * 16, Wh + off);
        }
    };

    load_stage(0);
    CP_COMMIT();
    load_stage(1);
    CP_COMMIT();

    for (int s = 0; s < 32; s++) {
        CP_WAIT(1);
        __syncthreads();
        if (s + 2 < 32) load_stage(s + 2);
        CP_COMMIT();
        uint32_t bb = sb + (s % 3) * AV_STAGE;
#pragma unroll
        for (int kk = 0; kk < 2; kk++) {
            uint32_t aBase = bb + (wm * 64 + (lane & 15)) * 80 + (lane >> 4) * 16 + kk * 32;
            uint32_t aHi[4][4];
#pragma unroll
            for (int mt = 0; mt < 4; mt++)
                ldm_x4(aHi[mt], aBase + mt * 16 * 80);
            uint32_t bBase = bb + AV_A_SZ + (kk * 16 + (lane & 15)) * 272 + wn * 64 +
                             ((lane >> 4) & 1) * 16;
#pragma unroll
            for (int pr = 0; pr < 2; pr++) {
                uint32_t bH[4];
                ldm_x4t(bH, bBase + pr * 32);
#pragma unroll
                for (int mt = 0; mt < 4; mt++)
#pragma unroll
                    for (int n2 = 0; n2 < 2; n2++)
                        mma_f16(acc[mt][pr * 2 + n2], aHi[mt], bH + 2 * n2);
            }
        }
    }

    // bias + relu + pool over this block's 128 rows
    float psum[4][2], pmax[4][2];
#pragma unroll
    for (int ntl = 0; ntl < 4; ntl++) {
        psum[ntl][0] = psum[ntl][1] = 0.f;
        pmax[ntl][0] = pmax[ntl][1] = 0.f;
    }
#pragma unroll
    for (int ntl = 0; ntl < 4; ntl++) {
        int c = e0 + wn * 32 + ntl * 8 + (lane & 3) * 2;
        float b0 = fb[c], b1 = fb[c + 1];
#pragma unroll
        for (int mt = 0; mt < 4; mt++) {
            float* cc = acc[mt][ntl];
            float v0 = fmaxf(cc[0] + b0, 0.f);
            float v1 = fmaxf(cc[1] + b1, 0.f);
            float v2 = fmaxf(cc[2] + b0, 0.f);
            float v3 = fmaxf(cc[3] + b1, 0.f);
            psum[ntl][0] += v0 + v2;
            psum[ntl][1] += v1 + v3;
            pmax[ntl][0] = fmaxf(pmax[ntl][0], fmaxf(v0, v2));
            pmax[ntl][1] = fmaxf(pmax[ntl][1], fmaxf(v1, v3));
        }
    }
    __syncthreads();
    float* redS = (float*)(smem + FU_RED_OFF);
    float* redM = redS + 256;
#pragma unroll
    for (int ntl = 0; ntl < 4; ntl++)
#pragma unroll
        for (int j = 0; j < 2; j++) {
            float s = psum[ntl][j], m = pmax[ntl][j];
            s += __shfl_xor_sync(0xffffffffu, s, 4);
            s += __shfl_xor_sync(0xffffffffu, s, 8);
            s += __shfl_xor_sync(0xffffffffu, s, 16);
            m = fmaxf(m, __shfl_xor_sync(0xffffffffu, m, 4));
            m = fmaxf(m, __shfl_xor_sync(0xffffffffu, m, 8));
            m = fmaxf(m, __shfl_xor_sync(0xffffffffu, m, 16));
            if (lane < 4) {
                int col = wn * 32 + ntl * 8 + lane * 2 + j;
                redS[wm * 128 + col] = s;
                redM[wm * 128 + col] = m;
            }
        }
    __syncthreads();
    if (t < 128) {
        float s = redS[t] + redS[128 + t];
        float m = fmaxf(redM[t], redM[128 + t]);
        int idx = (p * 4 + qt) * 512 + e0 + t;
        g_psum[idx] = s;
        g_pmax[idx] = m;
    }
}

// ---------------- out GEMM: k-split partials, pooling fused in ----------------
// (b, ks): ks<4 -> mean segment of pair p=4b+ks; ks>=4 -> max segment of pair 4b+ks-4
__global__ __launch_bounds__(256) void k_out_part(const float* __restrict__ ow) {
    __shared__ float sp[512];
    int b = blockIdx.x, ks = blockIdx.y, t = threadIdx.x;
    int p = b * 4 + (ks & 3);
    bool ismax = ks >= 4;
    for (int e = t; e < 512; e += 256) {
        if (ismax) {
            float m = g_pmax[(p * 4 + 0) * 512 + e];
            m = fmaxf(m, g_pmax[(p * 4 + 1) * 512 + e]);
            m = fmaxf(m, g_pmax[(p * 4 + 2) * 512 + e]);
            m = fmaxf(m, g_pmax[(p * 4 + 3) * 512 + e]);
            sp[e] = m;
        } else {
            float s = g_psum[(p * 4 + 0) * 512 + e] + g_psum[(p * 4 + 1) * 512 + e] +
                      g_psum[(p * 4 + 2) * 512 + e] + g_psum[(p * 4 + 3) * 512 + e];
            sp[e] = s * (1.0f / 512.0f);
        }
    }
    __syncthreads();
    int col = t * 4;
    float4 acc = make_float4(0.f, 0.f, 0.f, 0.f);
    int krow = (ismax ? 2048 : 0) + (ks & 3) * 512;
#pragma unroll 8
    for (int c = 0; c < 512; c++) {
        float pv = sp[c];
        float4 w = *(const float4*)(ow + (size_t)(krow + c) * 1024 + col);
        acc.x += pv * w.x;
        acc.y += pv * w.y;
        acc.z += pv * w.z;
        acc.w += pv * w.w;
    }
    *(float4*)(g_opart + ((size_t)ks * 32 + b) * 1024 + col) = acc;
}

// ---------------- out finalize: fixed-order sum + bias + relu ----------------
__global__ __launch_bounds__(256) void k_out_fin(const float* __restrict__ ob,
                                                 float* __restrict__ outp) {
    int b = blockIdx.x, col = threadIdx.x * 4;
    float4 acc = *(const float4*)(ob + col);
#pragma unroll
    for (int ks = 0; ks < 8; ks++) {
        float4 v = *(const float4*)(g_opart + ((size_t)ks * 32 + b) * 1024 + col);
        acc.x += v.x;
        acc.y += v.y;
        acc.z += v.z;
        acc.w += v.w;
    }
    acc.x = fmaxf(acc.x, 0.f);
    acc.y = fmaxf(acc.y, 0.f);
    acc.z = fmaxf(acc.z, 0.f);
    acc.w = fmaxf(acc.w, 0.f);
    *(float4*)(outp + b * 1024 + col) = acc;
}

extern "C" void kernel_launch(void* const* d_in, const int* in_sizes, int n_in,
                              void* d_out, int out_size) {
    const float* x1 = (const float*)d_in[0];
    const float* x2 = (const float*)d_in[1];
    const unsigned int* x1_len = (const unsigned int*)d_in[2];
    const unsigned int* x2_len = (const unsigned int*)d_in[3];
    const float* fw = (const float*)d_in[4];
    const float* fb = (const float*)d_in[5];
    const float* ow = (const float*)d_in[6];
    const float* ob = (const float*)d_in[7];

    float* outp = (float*)d_out;
    float* attn;
    if (out_size >= OUT_ELEMS + ATTN_ELEMS) {
        attn = outp + OUT_ELEMS;
    } else if (out_size >= ATTN_ELEMS) {
        attn = outp;
        void* dp = nullptr;
        cudaGetSymbolAddress(&dp, g_out_dummy);
        outp = (float*)dp;
    } else {
        void* dp = nullptr;
        cudaGetSymbolAddress(&dp, g_attn_scratch);
        attn = (float*)dp;
    }

    void *qh, *fwh;
    cudaGetSymbolAddress(&qh, g_qh);
    cudaGetSymbolAddress(&fwh, g_fwh);

    cudaFuncSetAttribute(k_scores_mma, cudaFuncAttributeMaxDynamicSharedMemorySize, SC_SMEM);
    cudaFuncSetAttribute(k_av_mma, cudaFuncAttributeMaxDynamicSharedMemorySize, AV_SMEM);
    cudaFuncSetAttribute(k_fusion_mma, cudaFuncAttributeMaxDynamicSharedMemorySize, FU_SMEM);

    k_lens<<<1, 128>>>(x1_len, x2_len);
    k_vmean_part<<<dim3(4, NPAIR), 512>>>(x2);
    k_vmean_fin<<<NPAIR, 512>>>();
    k_cvt1<<<8192, 256>>>(x1, (__half*)qh, 2097152);
    k_cvt1<<<512, 256>>>(fw, (__half*)fwh, 131072);
    k_scores_mma<<<dim3(4, NPAIR), 256, SC_SMEM>>>(attn);
    k_av_mma<<<dim3(4, 4, NPAIR), 256, AV_SMEM>>>(x1);
    k_fusion_mma<<<dim3(4, 4, NPAIR), 256, FU_SMEM>>>(fb);
    k_out_part<<<dim3(NB, 8), 256>>>(ow);
    k_out_fin<<<NB, 256>>>(ob, outp);
}

// round 17
// speedup vs baseline: 1.1136x; 1.0330x over previous
#include <cuda_runtime.h>
#include <cuda_fp16.h>
#include <cstdint>

#define CL 512
#define CE 512
#define NPAIR 128
#define NB 32
#define ATTN_ELEMS (NPAIR * CL * CL)
#define OUT_ELEMS (NB * 1024)
#define SCALE_F 0.044194173824159216f

// ---------------- scratch (device globals; alloc-free rule) ----------------
__device__ float g_attn_scratch[ATTN_ELEMS];
__device__ float g_out_dummy[OUT_ELEMS];
__device__ float g_rowsum[NPAIR * CL];
__device__ float g_psum[4 * NPAIR * CL];
__device__ float g_pmax[4 * NPAIR * CL];
__device__ float g_vmean[NPAIR * CE];
__device__ float g_vpart[4 * NPAIR * CE];
__device__ float g_opart[8 * NB * 1024];
__device__ int g_qlen[32];
__device__ int g_klen[128];
__device__ __half g_qh[NB * CL * CE];     // x1 fp16
__device__ __half g_kh[NPAIR * CL * CE];  // x2 fp16
__device__ __half g_ah[NPAIR * CL * CL];  // UNNORMALIZED exp fp16 (live region only)
__device__ __half g_sh[NPAIR * CL * CE];  // x1 - xa fp16
__device__ __half g_mh[NPAIR * CL * CE];  // x1 * xa fp16
__device__ __half g_fwh[1024 * 512];      // fusion_w fp16

// ---------------- PTX helpers ----------------
__device__ __forceinline__ uint32_t smem_u32(const void* p) {
    uint32_t a;
    asm("{ .reg .u64 t; cvta.to.shared.u64 t, %1; cvt.u32.u64 %0, t; }" : "=r"(a) : "l"(p));
    return a;
}
__device__ __forceinline__ void cp_async16(uint32_t dst, const void* src) {
    asm volatile("cp.async.ca.shared.global [%0], [%1], 16;" :: "r"(dst), "l"(src));
}
#define CP_COMMIT() asm volatile("cp.async.commit_group;" ::: "memory")
#define CP_WAIT(n)  asm volatile("cp.async.wait_group %0;" :: "n"(n) : "memory")

__device__ __forceinline__ void ldm_x4(uint32_t* r, uint32_t addr) {
    asm volatile("ldmatrix.sync.aligned.m8n8.x4.shared.b16 {%0,%1,%2,%3}, [%4];"
                 : "=r"(r[0]), "=r"(r[1]), "=r"(r[2]), "=r"(r[3]) : "r"(addr));
}
__device__ __forceinline__ void ldm_x4t(uint32_t* r, uint32_t addr) {
    asm volatile("ldmatrix.sync.aligned.m8n8.x4.trans.shared.b16 {%0,%1,%2,%3}, [%4];"
                 : "=r"(r[0]), "=r"(r[1]), "=r"(r[2]), "=r"(r[3]) : "r"(addr));
}
__device__ __forceinline__ void mma_f16(float* c, const uint32_t* a, const uint32_t* b) {
    asm volatile(
        "mma.sync.aligned.m16n8k16.row.col.f32.f16.f16.f32 "
        "{%0,%1,%2,%3}, {%4,%5,%6,%7}, {%8,%9}, {%0,%1,%2,%3};"
        : "+f"(c[0]), "+f"(c[1]), "+f"(c[2]), "+f"(c[3])
        : "r"(a[0]), "r"(a[1]), "r"(a[2]), "r"(a[3]), "r"(b[0]), "r"(b[1]));
}

// ---------------- smem geometry (3-stage rings, 128x128 tiles) ----------------
#define PITCHB 80
#define TILE_B (128 * PITCHB)           // 10240
#define SC_STAGE (2 * TILE_B)           // 20480
#define SC_RS_OFF (3 * SC_STAGE)        // 61440
#define SC_RINV_OFF (SC_RS_OFF + 2048)
#define SC_SMEM (SC_RINV_OFF + 512)
#define AV_A_SZ (128 * 80)              // 10240
#define AV_V_SZ (32 * 272)              // 8704
#define AV_STAGE (AV_A_SZ + AV_V_SZ)    // 18944
#define AV_SMEM (3 * AV_STAGE)          // 56832
#define FU_RED_OFF (3 * AV_STAGE)       // 56832
#define FU_SMEM (FU_RED_OFF + 2048)     // 58880

// ---------------- length normalization ----------------
__global__ void k_lens(const unsigned int* __restrict__ x1l,
                       const unsigned int* __restrict__ x2l) {
    __shared__ int is64;
    int t = threadIdx.x;
    if (t == 0) {
        int all0 = 1;
        for (int i = 1; i < 128; i += 2)
            if (x2l[i] != 0u) { all0 = 0; break; }
        is64 = all0;
    }
    __syncthreads();
    if (t < 32)  g_qlen[t] = (int)(is64 ? x1l[2 * t] : x1l[t]);
    if (t < 128) g_klen[t] = (int)(is64 ? x2l[2 * t] : x2l[t]);
}

// ---------------- V colmean partials + fused x2 -> fp16 conversion (k-split) -------
__global__ void k_vmean_part(const float* __restrict__ x2) {
    int p = blockIdx.y, kc = blockIdx.x * 128, e = threadIdx.x;
    const float* base = x2 + (size_t)p * 262144 + (size_t)kc * 512 + e;
    __half* kh = g_kh + (size_t)p * 262144 + (size_t)kc * 512 + e;
    float s0 = 0.f, s1 = 0.f, s2 = 0.f, s3 = 0.f;
    for (int k = 0; k < 128; k += 4) {
        float v0 = base[(k + 0) * 512];
        float v1 = base[(k + 1) * 512];
        float v2 = base[(k + 2) * 512];
        float v3 = base[(k + 3) * 512];
        s0 += v0; s1 += v1; s2 += v2; s3 += v3;
        kh[(k + 0) * 512] = __float2half(v0);
        kh[(k + 1) * 512] = __float2half(v1);
        kh[(k + 2) * 512] = __float2half(v2);
        kh[(k + 3) * 512] = __float2half(v3);
    }
    g_vpart[(p * 4 + blockIdx.x) * 512 + e] = (s0 + s1) + (s2 + s3);
}

__global__ void k_vmean_fin(void) {
    int p = blockIdx.x, e = threadIdx.x;
    float s = g_vpart[(p * 4 + 0) * 512 + e] + g_vpart[(p * 4 + 1) * 512 + e] +
              g_vpart[(p * 4 + 2) * 512 + e] + g_vpart[(p * 4 + 3) * 512 + e];
    g_vmean[p * 512 + e] = s * (1.f / 512.f);
}

// ---------------- fp32 -> fp16: x1 and fw in one launch ----------------
__global__ void k_cvt2(const float* __restrict__ x1, __half* __restrict__ qh,
                       const float* __restrict__ fw, __half* __restrict__ fwh) {
    int i = blockIdx.x * blockDim.x + threadIdx.x;
    const float* src;
    __half* dst;
    if (i < 2097152) {
        src = x1;
        dst = qh;
    } else {
        i -= 2097152;
        if (i >= 131072) return;
        src = fw;
        dst = fwh;
    }
    float4 v = ((const float4*)src)[i];
    ((__half2*)dst)[2 * i] = __floats2half2_rn(v.x, v.y);
    ((__half2*)dst)[2 * i + 1] = __floats2half2_rn(v.z, v.w);
}

// ---------------- scores: Q@K^T (1-term fp16), masked exp -> fp16 + fp32 attn -----
__global__ __launch_bounds__(256, 2) void k_scores_mma(float* __restrict__ attn) {
    extern __shared__ char smem[];
    uint32_t sb = smem_u32(smem);
    int t = threadIdx.x, lane = t & 31, wid = t >> 5;
    int wm = wid >> 2, wn = wid & 3;
    int p = blockIdx.y, x1i = p & 31;
    int qt = blockIdx.x, q0 = qt * 128;
    int qlen = g_qlen[x1i], klen = g_klen[p];

    bool all_masked = (q0 >= qlen) || (klen == 0);
    int n_nt = all_masked ? 0 : min(4, (klen + 127) >> 7);
    int n_stages = n_nt * 16;

    const char* Qh = (const char*)(g_qh + (size_t)x1i * 262144);
    const char* Kh = (const char*)(g_kh + (size_t)p * 262144);

    float acc[4][4][4];
#pragma unroll
    for (int a = 0; a < 4; a++)
#pragma unroll
        for (int b = 0; b < 4; b++)
#pragma unroll
            for (int c = 0; c < 4; c++) acc[a][b][c] = 0.f;
    float rsum[4][2];
#pragma unroll
    for (int a = 0; a < 4; a++) rsum[a][0] = rsum[a][1] = 0.f;

    auto load_stage = [&](int s) {
        int nt = s >> 4, ec = s & 15;
        uint32_t bb = sb + (s % 3) * SC_STAGE;
#pragma unroll
        for (int h = 0; h < 2; h++) {
            int idx = h * 256 + t;
            int row = idx >> 2, q = (idx & 3) * 16;
            uint32_t dst = row * PITCHB + q;
            size_t asrc = (size_t)(q0 + row) * 1024 + ec * 64 + q;
            size_t bsrc = (size_t)(nt * 128 + row) * 1024 + ec * 64 + q;
            cp_async16(bb + dst, Qh + asrc);
            cp_async16(bb + TILE_B + dst, Kh + bsrc);
        }
    };

    if (n_stages > 0) {
        load_stage(0);
        CP_COMMIT();
        if (n_stages > 1) load_stage(1);
        CP_COMMIT();
    }

    __half2* AH = (__half2*)(g_ah + (size_t)p * 262144);

    for (int s = 0; s < n_stages; s++) {
        CP_WAIT(1);
        __syncthreads();
        if (s + 2 < n_stages) load_stage(s + 2);
        CP_COMMIT();
        uint32_t bb = sb + (s % 3) * SC_STAGE;
#pragma unroll
        for (int kk = 0; kk < 2; kk++) {
            uint32_t aBase = bb + (wm * 64 + (lane & 15)) * PITCHB + (lane >> 4) * 16 +
                             kk * 32;
            uint32_t aHi[4][4];
#pragma unroll
            for (int mt = 0; mt < 4; mt++)
                ldm_x4(aHi[mt], aBase + mt * 16 * PITCHB);
            uint32_t bBase = bb + TILE_B +
                             (wn * 32 + ((lane >> 4) & 1) * 8 + (lane & 7)) * PITCHB +
                             ((lane >> 3) & 1) * 16 + kk * 32;
#pragma unroll
            for (int pr = 0; pr < 2; pr++) {
                uint32_t bH[4];
                ldm_x4(bH, bBase + pr * 16 * PITCHB);
#pragma unroll
                for (int mt = 0; mt < 4; mt++)
#pragma unroll
                    for (int n2 = 0; n2 < 2; n2++)
                        mma_f16(acc[mt][pr * 2 + n2], aHi[mt], bH + 2 * n2);
            }
        }
        if ((s & 15) == 15) {
            int nt = s >> 4;
            int nb = nt * 128 + wn * 32;
#pragma unroll
            for (int mt = 0; mt < 4; mt++) {
                int r0 = q0 + wm * 64 + mt * 16 + (lane >> 2);
                bool fm0 = (r0 >= qlen);
                bool fm1 = ((r0 + 8) >= qlen);
#pragma unroll
                for (int ntl = 0; ntl < 4; ntl++) {
                    int col = nb + ntl * 8 + (lane & 3) * 2;
                    float* cc = acc[mt][ntl];
                    if (!fm0) {
                        float e0 = (col < klen) ? __expf(cc[0] * SCALE_F) : 0.f;
                        float e1 = (col + 1 < klen) ? __expf(cc[1] * SCALE_F) : 0.f;
                        rsum[mt][0] += e0 + e1;
                        AH[((size_t)r0 * 512 + col) >> 1] = __floats2half2_rn(e0, e1);
                    }
                    if (!fm1) {
                        float e2 = (col < klen) ? __expf(cc[2] * SCALE_F) : 0.f;
                        float e3 = (col + 1 < klen) ? __expf(cc[3] * SCALE_F) : 0.f;
                        rsum[mt][1] += e2 + e3;
                        AH[((size_t)(r0 + 8) * 512 + col) >> 1] = __floats2half2_rn(e2, e3);
                    }
                    cc[0] = cc[1] = cc[2] = cc[3] = 0.f;
                }
            }
        }
    }

    __syncthreads();
    float* rs = (float*)(smem + SC_RS_OFF);
    float* rinv = (float*)(smem + SC_RINV_OFF);
#pragma unroll
    for (int mt = 0; mt < 4; mt++)
#pragma unroll
        for (int ri = 0; ri < 2; ri++) {
            float v = rsum[mt][ri];
            v += __shfl_xor_sync(0xffffffffu, v, 1);
            v += __shfl_xor_sync(0xffffffffu, v, 2);
            if ((lane & 3) == 0)
                rs[(wm * 64 + mt * 16 + ri * 8 + (lane >> 2)) * 4 + wn] = v;
        }
    __syncthreads();
    if (t < 128) {
        bool mr = all_masked || ((q0 + t) >= qlen);
        float s = mr ? 512.f
                     : (rs[t * 4] + rs[t * 4 + 1] + rs[t * 4 + 2] + rs[t * 4 + 3]);
        g_rowsum[p * 512 + q0 + t] = s;
        rinv[t] = 1.f / s;
    }
    __syncthreads();

    // normalize tail: masked rows -> 1/512 const; live rows -> normalize active
    // columns from just-written exp (L2-hot), zero beyond klen's 128-blocks.
    {
        const __half2* AHB = (const __half2*)(g_ah + (size_t)p * 262144);
        float* AT = attn + (size_t)p * 262144;
        int ncol = n_nt * 128;
        const float UNIF = 1.f / 512.f;
        for (int i = t; i < 128 * 128; i += 256) {
            int row = i >> 7, c4 = (i & 127) * 4;
            bool mr = all_masked || ((q0 + row) >= qlen);
            size_t o = (size_t)(q0 + row) * 512 + c4;
            float4 v;
            if (mr) {
                v = make_float4(UNIF, UNIF, UNIF, UNIF);
            } else if (c4 < ncol) {
                float inv = rinv[row];
                float2 f0 = __half22float2(AHB[o >> 1]);
                float2 f1 = __half22float2(AHB[(o >> 1) + 1]);
                v.x = f0.x * inv;
                v.y = f0.y * inv;
                v.z = f1.x * inv;
                v.w = f1.y * inv;
            } else {
                v = make_float4(0.f, 0.f, 0.f, 0.f);
            }
            *(float4*)(AT + o) = v;
        }
    }
}

// ---------------- x1_att = exp @ V / rowsum (1-term fp16); emits cat fp16 ----------
__global__ __launch_bounds__(256, 2) void k_av_mma(const float* __restrict__ x1) {
    extern __shared__ char smem[];
    uint32_t sb = smem_u32(smem);
    int t = threadIdx.x, lane = t & 31, wid = t >> 5;
    int wm = wid >> 2, wn = wid & 3;
    int p = blockIdx.z, x1i = p & 31;
    int q0 = blockIdx.y * 128, e0 = blockIdx.x * 128;
    int qlen = g_qlen[x1i], klen = g_klen[p];

    bool all_masked = (q0 >= qlen) || (klen == 0);
    int n_stage = all_masked ? 0 : min(16, (klen + 31) >> 5);

    const char* Ah = (const char*)(g_ah + (size_t)p * 262144);
    const char* Vh = (const char*)(g_kh + (size_t)p * 262144);

    float acc[4][4][4];
#pragma unroll
    for (int a = 0; a < 4; a++)
#pragma unroll
        for (int b = 0; b < 4; b++)
#pragma unroll
            for (int c = 0; c < 4; c++) acc[a][b][c] = 0.f;

    auto load_stage = [&](int s) {
        uint32_t bb = sb + (s % 3) * AV_STAGE;
#pragma unroll
        for (int h = 0; h < 2; h++) {
            int idx = h * 256 + t;
            int row = idx >> 2, ch = idx & 3;
            size_t off = (size_t)(q0 + row) * 1024 + s * 64 + ch * 16;
            cp_async16(bb + row * 80 + ch * 16, Ah + off);
        }
#pragma unroll
        for (int h = 0; h < 2; h++) {
            int idx = h * 256 + t;
            int row = idx >> 4, ch = idx & 15;
            size_t off = (size_t)(s * 32 + row) * 1024 + e0 * 2 + ch * 16;
            cp_async16(bb + AV_A_SZ + row * 272 + ch * 16, Vh + off);
        }
    };

    if (n_stage > 0) {
        load_stage(0);
        CP_COMMIT();
        if (n_stage > 1) load_stage(1);
        CP_COMMIT();
    }

    for (int s = 0; s < n_stage; s++) {
        CP_WAIT(1);
        __syncthreads();
        if (s + 2 < n_stage) load_stage(s + 2);
        CP_COMMIT();
        uint32_t bb = sb + (s % 3) * AV_STAGE;
#pragma unroll
        for (int kk = 0; kk < 2; kk++) {
            uint32_t aBase = bb + (wm * 64 + (lane & 15)) * 80 + (lane >> 4) * 16 + kk * 32;
            uint32_t aHi[4][4];
#pragma unroll
            for (int mt = 0; mt < 4; mt++)
                ldm_x4(aHi[mt], aBase + mt * 16 * 80);
            uint32_t bBase = bb + AV_A_SZ + (kk * 16 + (lane & 15)) * 272 + wn * 64 +
                             ((lane >> 4) & 1) * 16;
#pragma unroll
            for (int pr = 0; pr < 2; pr++) {
                uint32_t bH[4];
                ldm_x4t(bH, bBase + pr * 32);
#pragma unroll
                for (int mt = 0; mt < 4; mt++)
#pragma unroll
                    for (int n2 = 0; n2 < 2; n2++)
                        mma_f16(acc[mt][pr * 2 + n2], aHi[mt], bH + 2 * n2);
            }
        }
    }

    // epilogue: xa = acc/rowsum (masked rows: colmean V) -> (x1-xa, x1*xa) fp16
    const float* X1 = x1 + (size_t)x1i * 262144;
    const float* VM = g_vmean + p * 512;
    __half2* Sh = (__half2*)(g_sh + (size_t)p * 262144);
    __half2* Mh = (__half2*)(g_mh + (size_t)p * 262144);
#pragma unroll
    for (int mt = 0; mt < 4; mt++) {
#pragma unroll
        for (int hh = 0; hh < 2; hh++) {
            int r = q0 + wm * 64 + mt * 16 + (lane >> 2) + hh * 8;
            bool mr = all_masked || (r >= qlen);
            float inv = 0.f;
            if (!mr) inv = 1.f / g_rowsum[p * 512 + r];
#pragma unroll
            for (int ntl = 0; ntl < 4; ntl++) {
                float* cc = acc[mt][ntl];
                int c = e0 + wn * 32 + ntl * 8 + (lane & 3) * 2;
                float2 u = *(const float2*)(X1 + (size_t)r * 512 + c);
                float xa0, xa1;
                if (mr) {
                    float2 vm = *(const float2*)(VM + c);
                    xa0 = vm.x;
                    xa1 = vm.y;
                } else {
                    xa0 = cc[hh * 2] * inv;
                    xa1 = cc[hh * 2 + 1] * inv;
                }
                size_t o = ((size_t)r * 512 + c) >> 1;
                Sh[o] = __floats2half2_rn(u.x - xa0, u.y - xa1);
                Mh[o] = __floats2half2_rn(u.x * xa0, u.y * xa1);
            }
        }
    }
}

// ---------------- fusion GEMM (1-term fp16) + bias/relu + partial pooling ----------
__global__ __launch_bounds__(256, 2) void k_fusion_mma(const float* __restrict__ fb) {
    extern __shared__ char smem[];
    uint32_t sb = smem_u32(smem);
    int t = threadIdx.x, lane = t & 31, wid = t >> 5;
    int wm = wid >> 2, wn = wid & 3;
    int p = blockIdx.z;
    int qt = blockIdx.y, q0 = qt * 128, e0 = blockIdx.x * 128;

    const char* Sh = (const char*)(g_sh + (size_t)p * 262144);
    const char* Mh = (const char*)(g_mh + (size_t)p * 262144);
    const char* Wh = (const char*)g_fwh;

    float acc[4][4][4];
#pragma unroll
    for (int a = 0; a < 4; a++)
#pragma unroll
        for (int b = 0; b < 4; b++)
#pragma unroll
            for (int c = 0; c < 4; c++) acc[a][b][c] = 0.f;

    auto load_stage = [&](int s) {
        uint32_t bb = sb + (s % 3) * AV_STAGE;
        const char* ah = (s < 16) ? Sh : Mh;
        int kc = (s & 15) * 64;
#pragma unroll
        for (int h = 0; h < 2; h++) {
            int idx = h * 256 + t;
            int row = idx >> 2, ch = idx & 3;
            size_t off = (size_t)(q0 + row) * 1024 + kc + ch * 16;
            cp_async16(bb + row * 80 + ch * 16, ah + off);
        }
#pragma unroll
        for (int h = 0; h < 2; h++) {
            int idx = h * 256 + t;
            int row = idx >> 4, ch = idx & 15;
            size_t off = (size_t)(s * 32 + row) * 1024 + e0 * 2 + ch * 16;
            cp_async16(bb + AV_A_SZ + row * 272 + ch * 16, Wh + off);
        }
    };

    load_stage(0);
    CP_COMMIT();
    load_stage(1);
    CP_COMMIT();

    for (int s = 0; s < 32; s++) {
        CP_WAIT(1);
        __syncthreads();
        if (s + 2 < 32) load_stage(s + 2);
        CP_COMMIT();
        uint32_t bb = sb + (s % 3) * AV_STAGE;
#pragma unroll
        for (int kk = 0; kk < 2; kk++) {
            uint32_t aBase = bb + (wm * 64 + (lane & 15)) * 80 + (lane >> 4) * 16 + kk * 32;
            uint32_t aHi[4][4];
#pragma unroll
            for (int mt = 0; mt < 4; mt++)
                ldm_x4(aHi[mt], aBase + mt * 16 * 80);
            uint32_t bBase = bb + AV_A_SZ + (kk * 16 + (lane & 15)) * 272 + wn * 64 +
                             ((lane >> 4) & 1) * 16;
#pragma unroll
            for (int pr = 0; pr < 2; pr++) {
                uint32_t bH[4];
                ldm_x4t(bH, bBase + pr * 32);
#pragma unroll
                for (int mt = 0; mt < 4; mt++)
#pragma unroll
                    for (int n2 = 0; n2 < 2; n2++)
                        mma_f16(acc[mt][pr * 2 + n2], aHi[mt], bH + 2 * n2);
            }
        }
    }

    // bias + relu + pool over this block's 128 rows
    float psum[4][2], pmax[4][2];
#pragma unroll
    for (int ntl = 0; ntl < 4; ntl++) {
        psum[ntl][0] = psum[ntl][1] = 0.f;
        pmax[ntl][0] = pmax[ntl][1] = 0.f;
    }
#pragma unroll
    for (int ntl = 0; ntl < 4; ntl++) {
        int c = e0 + wn * 32 + ntl * 8 + (lane & 3) * 2;
        float b0 = fb[c], b1 = fb[c + 1];
#pragma unroll
        for (int mt = 0; mt < 4; mt++) {
            float* cc = acc[mt][ntl];
            float v0 = fmaxf(cc[0] + b0, 0.f);
            float v1 = fmaxf(cc[1] + b1, 0.f);
            float v2 = fmaxf(cc[2] + b0, 0.f);
            float v3 = fmaxf(cc[3] + b1, 0.f);
            psum[ntl][0] += v0 + v2;
            psum[ntl][1] += v1 + v3;
            pmax[ntl][0] = fmaxf(pmax[ntl][0], fmaxf(v0, v2));
            pmax[ntl][1] = fmaxf(pmax[ntl][1], fmaxf(v1, v3));
        }
    }
    __syncthreads();
    float* redS = (float*)(smem + FU_RED_OFF);
    float* redM = redS + 256;
#pragma unroll
    for (int ntl = 0; ntl < 4; ntl++)
#pragma unroll
        for (int j = 0; j < 2; j++) {
            float s = psum[ntl][j], m = pmax[ntl][j];
            s += __shfl_xor_sync(0xffffffffu, s, 4);
            s += __shfl_xor_sync(0xffffffffu, s, 8);
            s += __shfl_xor_sync(0xffffffffu, s, 16);
            m = fmaxf(m, __shfl_xor_sync(0xffffffffu, m, 4));
            m = fmaxf(m, __shfl_xor_sync(0xffffffffu, m, 8));
            m = fmaxf(m, __shfl_xor_sync(0xffffffffu, m, 16));
            if (lane < 4) {
                int col = wn * 32 + ntl * 8 + lane * 2 + j;
                redS[wm * 128 + col] = s;
                redM[wm * 128 + col] = m;
            }
        }
    __syncthreads();
    if (t < 128) {
        float s = redS[t] + redS[128 + t];
        float m = fmaxf(redM[t], redM[128 + t]);
        int idx = (p * 4 + qt) * 512 + e0 + t;
        g_psum[idx] = s;
        g_pmax[idx] = m;
    }
}

// ---------------- out GEMM: k-split partials, pooling fused in ----------------
__global__ __launch_bounds__(256) void k_out_part(const float* __restrict__ ow) {
    __shared__ float sp[512];
    int b = blockIdx.x, ks = blockIdx.y, t = threadIdx.x;
    int p = b * 4 + (ks & 3);
    bool ismax = ks >= 4;
    for (int e = t; e < 512; e += 256) {
        if (ismax) {
            float m = g_pmax[(p * 4 + 0) * 512 + e];
            m = fmaxf(m, g_pmax[(p * 4 + 1) * 512 + e]);
            m = fmaxf(m, g_pmax[(p * 4 + 2) * 512 + e]);
            m = fmaxf(m, g_pmax[(p * 4 + 3) * 512 + e]);
            sp[e] = m;
        } else {
            float s = g_psum[(p * 4 + 0) * 512 + e] + g_psum[(p * 4 + 1) * 512 + e] +
                      g_psum[(p * 4 + 2) * 512 + e] + g_psum[(p * 4 + 3) * 512 + e];
            sp[e] = s * (1.0f / 512.0f);
        }
    }
    __syncthreads();
    int col = t * 4;
    float4 acc = make_float4(0.f, 0.f, 0.f, 0.f);
    int krow = (ismax ? 2048 : 0) + (ks & 3) * 512;
#pragma unroll 8
    for (int c = 0; c < 512; c++) {
        float pv = sp[c];
        float4 w = *(const float4*)(ow + (size_t)(krow + c) * 1024 + col);
        acc.x += pv * w.x;
        acc.y += pv * w.y;
        acc.z += pv * w.z;
        acc.w += pv * w.w;
    }
    *(float4*)(g_opart + ((size_t)ks * 32 + b) * 1024 + col) = acc;
}

// ---------------- out finalize: fixed-order sum + bias + relu ----------------
__global__ __launch_bounds__(256) void k_out_fin(const float* __restrict__ ob,
                                                 float* __restrict__ outp) {
    int b = blockIdx.x, col = threadIdx.x * 4;
    float4 acc = *(const float4*)(ob + col);
#pragma unroll
    for (int ks = 0; ks < 8; ks++) {
        float4 v = *(const float4*)(g_opart + ((size_t)ks * 32 + b) * 1024 + col);
        acc.x += v.x;
        acc.y += v.y;
        acc.z += v.z;
        acc.w += v.w;
    }
    acc.x = fmaxf(acc.x, 0.f);
    acc.y = fmaxf(acc.y, 0.f);
    acc.z = fmaxf(acc.z, 0.f);
    acc.w = fmaxf(acc.w, 0.f);
    *(float4*)(outp + b * 1024 + col) = acc;
}

extern "C" void kernel_launch(void* const* d_in, const int* in_sizes, int n_in,
                              void* d_out, int out_size) {
    const float* x1 = (const float*)d_in[0];
    const float* x2 = (const float*)d_in[1];
    const unsigned int* x1_len = (const unsigned int*)d_in[2];
    const unsigned int* x2_len = (const unsigned int*)d_in[3];
    const float* fw = (const float*)d_in[4];
    const float* fb = (const float*)d_in[5];
    const float* ow = (const float*)d_in[6];
    const float* ob = (const float*)d_in[7];

    float* outp = (float*)d_out;
    float* attn;
    if (out_size >= OUT_ELEMS + ATTN_ELEMS) {
        attn = outp + OUT_ELEMS;
    } else if (out_size >= ATTN_ELEMS) {
        attn = outp;
        void* dp = nullptr;
        cudaGetSymbolAddress(&dp, g_out_dummy);
        outp = (float*)dp;
    } else {
        void* dp = nullptr;
        cudaGetSymbolAddress(&dp, g_attn_scratch);
        attn = (float*)dp;
    }

    void *qh, *fwh;
    cudaGetSymbolAddress(&qh, g_qh);
    cudaGetSymbolAddress(&fwh, g_fwh);

    cudaFuncSetAttribute(k_scores_mma, cudaFuncAttributeMaxDynamicSharedMemorySize, SC_SMEM);
    cudaFuncSetAttribute(k_av_mma, cudaFuncAttributeMaxDynamicSharedMemorySize, AV_SMEM);
    cudaFuncSetAttribute(k_fusion_mma, cudaFuncAttributeMaxDynamicSharedMemorySize, FU_SMEM);

    k_lens<<<1, 128>>>(x1_len, x2_len);
    k_vmean_part<<<dim3(4, NPAIR), 512>>>(x2);
    k_vmean_fin<<<NPAIR, 512>>>();
    k_cvt2<<<8704, 256>>>(x1, (__half*)qh, fw, (__half*)fwh);
    k_scores_mma<<<dim3(4, NPAIR), 256, SC_SMEM>>>(attn);
    k_av_mma<<<dim3(4, 4, NPAIR), 256, AV_SMEM>>>(x1);
    k_fusion_mma<<<dim3(4, 4, NPAIR), 256, FU_SMEM>>>(fb);
    k_out_part<<<dim3(NB, 8), 256>>>(ow);
    k_out_fin<<<NB, 256>>>(ob, outp);
}